// round 9
// baseline (speedup 1.0000x reference)
#include <cuda_runtime.h>
#include <cuda_bf16.h>
#include <stdint.h>

#define B_   4
#define S_   2048
#define D_   512
#define H_   8
#define HD_  64
#define ROWS_ (B_ * S_)          // 8192
#define EPS_ 1e-8f

// ---------------------------------------------------------------------------
// Scratch (__device__ globals; allocations are forbidden)
// ---------------------------------------------------------------------------
__device__ float g_Q    [(size_t)ROWS_ * D_];   // [B,H,S,HD]
__device__ float g_K    [(size_t)ROWS_ * D_];   // [B,H,S,HD]
__device__ float g_V    [(size_t)ROWS_ * D_];   // [B,H,S,HD]
__device__ float g_attn [(size_t)ROWS_ * D_];   // [B,S,D]
// fused activations, pre-split bf16 hi/lo (fp32 copy never needed)
__device__ unsigned short g_fus_h[(size_t)ROWS_ * D_];
__device__ unsigned short g_fus_l[(size_t)ROWS_ * D_];
// Weights transposed to [N][K], split bf16 hi/lo
__device__ unsigned short g_Wf_h[(size_t)D_ * 2 * D_];
__device__ unsigned short g_Wf_l[(size_t)D_ * 2 * D_];
__device__ unsigned short g_Wq_h[(size_t)D_ * D_];
__device__ unsigned short g_Wq_l[(size_t)D_ * D_];
__device__ unsigned short g_Wk_h[(size_t)D_ * D_];
__device__ unsigned short g_Wk_l[(size_t)D_ * D_];
__device__ unsigned short g_Wv_h[(size_t)D_ * D_];
__device__ unsigned short g_Wv_l[(size_t)D_ * D_];
__device__ unsigned short g_Wo_h[(size_t)D_ * D_];
__device__ unsigned short g_Wo_l[(size_t)D_ * D_];

// ---------------------------------------------------------------------------
// sm_80-level PTX helpers (NO tcgen05 — build target is plain sm_103)
// ---------------------------------------------------------------------------
__device__ __forceinline__ uint32_t smem_u32(const void* p) {
    uint32_t a;
    asm("{ .reg .u64 t; cvta.to.shared.u64 t, %1; cvt.u32.u64 %0, t; }"
        : "=r"(a) : "l"(p));
    return a;
}
__device__ __forceinline__ void ldm4(uint32_t addr, uint32_t* r) {
    asm volatile("ldmatrix.sync.aligned.m8n8.x4.shared.b16 {%0,%1,%2,%3}, [%4];"
                 : "=r"(r[0]), "=r"(r[1]), "=r"(r[2]), "=r"(r[3]) : "r"(addr));
}
__device__ __forceinline__ void mma_bf16(float* c, const uint32_t* a,
                                         const uint32_t* b) {
    asm volatile("mma.sync.aligned.m16n8k16.row.col.f32.bf16.bf16.f32 "
                 "{%0,%1,%2,%3}, {%4,%5,%6,%7}, {%8,%9}, {%0,%1,%2,%3};"
                 : "+f"(c[0]), "+f"(c[1]), "+f"(c[2]), "+f"(c[3])
                 : "r"(a[0]), "r"(a[1]), "r"(a[2]), "r"(a[3]),
                   "r"(b[0]), "r"(b[1]));
}
#define CP_ASYNC16(dst, src) \
    asm volatile("cp.async.ca.shared.global [%0], [%1], 16;" \
                 :: "r"(dst), "l"(src))
#define CP_COMMIT() asm volatile("cp.async.commit_group;" ::: "memory")
#define CP_WAIT0()  asm volatile("cp.async.wait_group 0;" ::: "memory")
#define CP_WAIT1()  asm volatile("cp.async.wait_group 1;" ::: "memory")

__device__ __forceinline__ void bsplit(float v, unsigned short& h,
                                       unsigned short& l) {
    __nv_bfloat16 hb = __float2bfloat16(v);
    float r = v - __bfloat162float(hb);
    __nv_bfloat16 lb = __float2bfloat16(r);
    h = __bfloat16_as_ushort(hb);
    l = __bfloat16_as_ushort(lb);
}

// ---------------------------------------------------------------------------
// Batched weight preconvert (ONE launch): W[K][N] -> Wt[N][K] bf16 hi/lo
// ---------------------------------------------------------------------------
__global__ void wconv_all(
    const float* __restrict__ Wf, const float* __restrict__ Wq,
    const float* __restrict__ Wk, const float* __restrict__ Wv,
    const float* __restrict__ Wo,
    unsigned short* __restrict__ Wfh, unsigned short* __restrict__ Wfl,
    unsigned short* __restrict__ Wqh, unsigned short* __restrict__ Wql,
    unsigned short* __restrict__ Wkh, unsigned short* __restrict__ Wkl,
    unsigned short* __restrict__ Wvh, unsigned short* __restrict__ Wvl,
    unsigned short* __restrict__ Woh, unsigned short* __restrict__ Wol)
{
    const float* W; unsigned short *Th, *Tl; int K;
    switch (blockIdx.z) {
        case 0:  W = Wf; Th = Wfh; Tl = Wfl; K = 1024; break;
        case 1:  W = Wq; Th = Wqh; Tl = Wql; K = 512;  break;
        case 2:  W = Wk; Th = Wkh; Tl = Wkl; K = 512;  break;
        case 3:  W = Wv; Th = Wvh; Tl = Wvl; K = 512;  break;
        default: W = Wo; Th = Woh; Tl = Wol; K = 512;  break;
    }
    int k0 = blockIdx.y * 32, n0 = blockIdx.x * 32;
    if (k0 >= K) return;
    __shared__ float t[32][33];
    int tx = threadIdx.x, ty = threadIdx.y;
    t[ty][tx] = W[(size_t)(k0 + ty) * D_ + n0 + tx];
    __syncthreads();
    float v = t[tx][ty];                 // W[k0+tx][n0+ty]
    unsigned short h, l;
    bsplit(v, h, l);
    size_t o = (size_t)(n0 + ty) * K + k0 + tx;
    Th[o] = h;
    Tl[o] = l;
}

// ---------------------------------------------------------------------------
// 3xBF16 tensor-core GEMM: C[M,N] = A[M,K] @ W[K,N] + bias
// CTA 128x128, K-chunk 32, 8 warps (2x4) of 64x32, 2-stage cp.async pipeline.
// __launch_bounds__(256,2): 2 CTAs/SM (regs=128 -> exactly fills the RF).
// ---------------------------------------------------------------------------
#define GSTAGE   40960
#define GOFF_AH  0
#define GOFF_AL  10240
#define GOFF_BH  20480
#define GOFF_BL  30720
#define GM_SMEM  (2 * GSTAGE)

__device__ __forceinline__ void gemm_ldA(const float* A0, const float* A1,
                                         int sA0, int sA1, int Ksplit,
                                         int bm, int k0, int tid, float4* av)
{
#pragma unroll
    for (int i = 0; i < 4; i++) {
        int fid = tid + i * 256;
        int m = fid >> 3, kq = fid & 7;
        int kg = k0 + kq * 4;
        const float* src = (kg < Ksplit)
            ? A0 + (size_t)(bm + m) * sA0 + kg
            : A1 + (size_t)(bm + m) * sA1 + (kg - Ksplit);
        av[i] = *(const float4*)src;
    }
}
__device__ __forceinline__ void gemm_stA(unsigned char* stage, int tid,
                                         const float4* av)
{
#pragma unroll
    for (int i = 0; i < 4; i++) {
        int fid = tid + i * 256;
        int m = fid >> 3, kq = fid & 7;
        ushort4 h, l;
        bsplit(av[i].x, h.x, l.x);
        bsplit(av[i].y, h.y, l.y);
        bsplit(av[i].z, h.z, l.z);
        bsplit(av[i].w, h.w, l.w);
        *(ushort4*)(stage + GOFF_AH + m * 80 + kq * 8) = h;
        *(ushort4*)(stage + GOFF_AL + m * 80 + kq * 8) = l;
    }
}
__device__ __forceinline__ void gemm_cpPre(uint32_t stage_u32,
                                           uint32_t offH, uint32_t offL,
                                           const unsigned short* Th,
                                           const unsigned short* Tl,
                                           int row0, int K, int k0, int tid)
{
#pragma unroll
    for (int i = 0; i < 2; i++) {
        int fid = tid + i * 256;
        int r = fid >> 2, c16 = fid & 3;
        size_t gs = (size_t)(row0 + r) * K + k0 + c16 * 8;
        CP_ASYNC16(stage_u32 + offH + r * 80 + c16 * 16, (const char*)(Th + gs));
        CP_ASYNC16(stage_u32 + offL + r * 80 + c16 * 16, (const char*)(Tl + gs));
    }
}

template <int MODE, int ASRC>
__global__ __launch_bounds__(256, 2) void mm_mma(
    const float* __restrict__ A0, const float* __restrict__ A1,
    int sA0, int sA1, int Ksplit,
    const unsigned short* __restrict__ Ah, const unsigned short* __restrict__ Al,
    const unsigned short* __restrict__ Bh, const unsigned short* __restrict__ Bl,
    const float* __restrict__ bias, float* __restrict__ C,
    unsigned short* __restrict__ Ch, unsigned short* __restrict__ Cl,
    int N, int K)
{
    extern __shared__ __align__(16) unsigned char smem[];
    const uint32_t sb = smem_u32(smem);
    const int tid = threadIdx.x, lane = tid & 31, wid = tid >> 5;
    const int wy = wid >> 2, wx = wid & 3;
    const int bn = blockIdx.x * 128, bm = blockIdx.y * 128;
    const int NC = K / 32;

    float acc[4][4][4];
#pragma unroll
    for (int i = 0; i < 4; i++)
#pragma unroll
        for (int j = 0; j < 4; j++)
#pragma unroll
            for (int q = 0; q < 4; q++) acc[i][j][q] = 0.f;

    const uint32_t arow = (wy * 64 + (lane & 15)) * 80 + (lane >> 4) * 16;
    const uint32_t brow = (wx * 32 + (lane & 15)) * 80 + (lane >> 4) * 16;

    float4 av[4];
    if (ASRC == 0) {
        gemm_ldA(A0, A1, sA0, sA1, Ksplit, bm, 0, tid, av);
        gemm_cpPre(sb, GOFF_BH, GOFF_BL, Bh, Bl, bn, K, 0, tid);
        CP_COMMIT();
        gemm_stA(smem, tid, av);
    } else {
        gemm_cpPre(sb, GOFF_AH, GOFF_AL, Ah, Al, bm, K, 0, tid);
        gemm_cpPre(sb, GOFF_BH, GOFF_BL, Bh, Bl, bn, K, 0, tid);
        CP_COMMIT();
    }

    for (int c = 0; c < NC; c++) {
        const int st = c & 1;
        const bool more = (c + 1 < NC);
        if (more) {
            uint32_t s1 = sb + ((c + 1) & 1) * GSTAGE;
            if (ASRC == 0) {
                gemm_ldA(A0, A1, sA0, sA1, Ksplit, bm, (c + 1) * 32, tid, av);
            } else {
                gemm_cpPre(s1, GOFF_AH, GOFF_AL, Ah, Al, bm, K, (c + 1) * 32, tid);
            }
            gemm_cpPre(s1, GOFF_BH, GOFF_BL, Bh, Bl, bn, K, (c + 1) * 32, tid);
            CP_COMMIT();
        }
        if (more) { CP_WAIT1(); } else { CP_WAIT0(); }
        __syncthreads();

        const uint32_t s0 = sb + st * GSTAGE;
#pragma unroll
        for (int ks = 0; ks < 2; ks++) {
            uint32_t ah[4][4], al[4][4];
#pragma unroll
            for (int mt = 0; mt < 4; mt++) {
                ldm4(s0 + GOFF_AH + arow + mt * 1280 + ks * 32, ah[mt]);
                ldm4(s0 + GOFF_AL + arow + mt * 1280 + ks * 32, al[mt]);
            }
#pragma unroll
            for (int nb = 0; nb < 2; nb++) {
                uint32_t bh4[4], bl4[4];
                ldm4(s0 + GOFF_BH + brow + nb * 1280 + ks * 32, bh4);
                ldm4(s0 + GOFF_BL + brow + nb * 1280 + ks * 32, bl4);
                uint32_t th0[2] = {bh4[0], bh4[2]}, th1[2] = {bh4[1], bh4[3]};
                uint32_t tl0[2] = {bl4[0], bl4[2]}, tl1[2] = {bl4[1], bl4[3]};
#pragma unroll
                for (int mt = 0; mt < 4; mt++) {
                    mma_bf16(acc[mt][2 * nb],     ah[mt], th0);
                    mma_bf16(acc[mt][2 * nb + 1], ah[mt], th1);
                    mma_bf16(acc[mt][2 * nb],     ah[mt], tl0);
                    mma_bf16(acc[mt][2 * nb + 1], ah[mt], tl1);
                    mma_bf16(acc[mt][2 * nb],     al[mt], th0);
                    mma_bf16(acc[mt][2 * nb + 1], al[mt], th1);
                }
            }
        }
        if (ASRC == 0 && more) gemm_stA(smem + ((c + 1) & 1) * GSTAGE, tid, av);
        __syncthreads();
    }

    // epilogue
#pragma unroll
    for (int mt = 0; mt < 4; mt++) {
#pragma unroll
        for (int nt = 0; nt < 4; nt++) {
            int r0 = bm + wy * 64 + mt * 16 + (lane >> 2);
            int col = bn + wx * 32 + nt * 8 + 2 * (lane & 3);
            float b0 = bias[col], b1 = bias[col + 1];
            float2 v0 = make_float2(acc[mt][nt][0] + b0, acc[mt][nt][1] + b1);
            float2 v1 = make_float2(acc[mt][nt][2] + b0, acc[mt][nt][3] + b1);
            if (MODE == 0) {
                *(float2*)(C + (size_t)r0 * N + col) = v0;
                *(float2*)(C + (size_t)(r0 + 8) * N + col) = v1;
            } else if (MODE == 1) {
                int hh = col >> 6, dd = col & (HD_ - 1);
                int bb0 = r0 >> 11, ss0 = r0 & (S_ - 1);
                *(float2*)(C + (((size_t)bb0 * H_ + hh) * S_ + ss0) * HD_ + dd) = v0;
                int r1 = r0 + 8;
                int bb1 = r1 >> 11, ss1 = r1 & (S_ - 1);
                *(float2*)(C + (((size_t)bb1 * H_ + hh) * S_ + ss1) * HD_ + dd) = v1;
            } else {
                unsigned short hx, lx, hy, ly;
                bsplit(v0.x, hx, lx); bsplit(v0.y, hy, ly);
                *(ushort2*)(Ch + (size_t)r0 * N + col) = make_ushort2(hx, hy);
                *(ushort2*)(Cl + (size_t)r0 * N + col) = make_ushort2(lx, ly);
                bsplit(v1.x, hx, lx); bsplit(v1.y, hy, ly);
                *(ushort2*)(Ch + (size_t)(r0 + 8) * N + col) = make_ushort2(hx, hy);
                *(ushort2*)(Cl + (size_t)(r0 + 8) * N + col) = make_ushort2(lx, ly);
            }
        }
    }
}

// ---------------------------------------------------------------------------
// Tensor-core flash attention, masked softmax + L1 renorm.
// CTA: 64 q-rows x one (b,h); 128 threads = 4 warps x 16 rows; 64-key blocks.
// 88 KB smem -> 2 CTAs/SM (cross-CTA overlap hides softmax + LDG latency).
// M double-buffered via cp.async; K/V prefetched into registers 1 block ahead.
// ---------------------------------------------------------------------------
#define OQH 0
#define OQL 9216
#define OKH 18432
#define OKL 27648
#define OVH 36864
#define OVL 46080
#define OMS 55296
#define MSTG 17408
#define ATTN_SMEM (55296 + 2 * 17408)   // 90112

__device__ __forceinline__ void attn_ldkv(const float* Kp, const float* Vp,
                                          int kk0, int tid,
                                          float4* kr, float4* vr)
{
#pragma unroll
    for (int i = 0; i < 4; i++) {
        int fid = tid + i * 128;
        int row = fid >> 4, c4 = (fid & 15) * 4;
        kr[i] = *(const float4*)(Kp + (size_t)(kk0 + row) * HD_ + c4);
        vr[i] = *(const float4*)(Vp + (size_t)(kk0 + row) * HD_ + c4);
    }
#pragma unroll
    for (int i = 4; i < 8; i++) {
        int fid = tid + i * 128;
        int row = fid >> 4, c4 = (fid & 15) * 4;
        kr[i] = *(const float4*)(Kp + (size_t)(kk0 + row) * HD_ + c4);
        vr[i] = *(const float4*)(Vp + (size_t)(kk0 + row) * HD_ + c4);
    }
}
__device__ __forceinline__ void attn_stkv(unsigned char* smem, int tid,
                                          const float4* kr, const float4* vr)
{
#pragma unroll
    for (int i = 0; i < 8; i++) {
        int fid = tid + i * 128;
        int row = fid >> 4, c4 = (fid & 15) * 4;
        ushort4 kh, kl;
        bsplit(kr[i].x, kh.x, kl.x); bsplit(kr[i].y, kh.y, kl.y);
        bsplit(kr[i].z, kh.z, kl.z); bsplit(kr[i].w, kh.w, kl.w);
        *(ushort4*)(smem + OKH + row * 144 + c4 * 2) = kh;
        *(ushort4*)(smem + OKL + row * 144 + c4 * 2) = kl;
        unsigned short vh, vl;
        bsplit(vr[i].x, vh, vl);
        *(unsigned short*)(smem + OVH + (c4 + 0) * 144 + row * 2) = vh;
        *(unsigned short*)(smem + OVL + (c4 + 0) * 144 + row * 2) = vl;
        bsplit(vr[i].y, vh, vl);
        *(unsigned short*)(smem + OVH + (c4 + 1) * 144 + row * 2) = vh;
        *(unsigned short*)(smem + OVL + (c4 + 1) * 144 + row * 2) = vl;
        bsplit(vr[i].z, vh, vl);
        *(unsigned short*)(smem + OVH + (c4 + 2) * 144 + row * 2) = vh;
        *(unsigned short*)(smem + OVL + (c4 + 2) * 144 + row * 2) = vl;
        bsplit(vr[i].w, vh, vl);
        *(unsigned short*)(smem + OVH + (c4 + 3) * 144 + row * 2) = vh;
        *(unsigned short*)(smem + OVL + (c4 + 3) * 144 + row * 2) = vl;
    }
}
__device__ __forceinline__ void attn_cpM(uint32_t sb, int stage,
                                         const float* Mp, int q0, int kk0,
                                         int tid)
{
#pragma unroll
    for (int i = 0; i < 8; i++) {
        int fid = tid + i * 128;
        int row = fid >> 4, c16 = fid & 15;
        CP_ASYNC16(sb + OMS + stage * MSTG + row * 272 + c16 * 16,
                   (const char*)(Mp + (size_t)(q0 + row) * S_ + kk0 + c16 * 4));
    }
}

__global__ __launch_bounds__(128, 2) void attn_mma(
    const float* __restrict__ Q, const float* __restrict__ K,
    const float* __restrict__ V, const float* __restrict__ Mm,
    float* __restrict__ Out)
{
    extern __shared__ __align__(16) unsigned char smem[];
    const uint32_t sb = smem_u32(smem);

    const int q0 = blockIdx.x * 64;
    const int h  = blockIdx.y;
    const int b  = blockIdx.z;
    const int tid = threadIdx.x, lane = tid & 31, w = tid >> 5;
    const int qr = lane >> 2, qc = lane & 3;

    const size_t bh = (size_t)b * H_ + h;
    const float* Qp = Q + bh * S_ * HD_;
    const float* Kp = K + bh * S_ * HD_;
    const float* Vp = V + bh * S_ * HD_;
    const float* Mp = Mm + (size_t)b * S_ * S_;

    // prologue: M(0) in flight, K/V(0) in registers
    attn_cpM(sb, 0, Mp, q0, 0, tid);
    CP_COMMIT();
    float4 kr[8], vr[8];
    attn_ldkv(Kp, Vp, 0, tid, kr, vr);

    // load Q tile (64x64), split to bf16 hi/lo
#pragma unroll
    for (int i = 0; i < 8; i++) {
        int fid = tid + i * 128;
        int row = fid >> 4, c4 = (fid & 15) * 4;
        float4 v = *(const float4*)(Qp + (size_t)(q0 + row) * HD_ + c4);
        ushort4 hh, ll;
        bsplit(v.x, hh.x, ll.x); bsplit(v.y, hh.y, ll.y);
        bsplit(v.z, hh.z, ll.z); bsplit(v.w, hh.w, ll.w);
        *(ushort4*)(smem + OQH + row * 144 + c4 * 2) = hh;
        *(ushort4*)(smem + OQL + row * 144 + c4 * 2) = ll;
    }

    float O[8][4];
#pragma unroll
    for (int t = 0; t < 8; t++)
#pragma unroll
        for (int j = 0; j < 4; j++) O[t][j] = 0.f;
    float m0 = -1e30f, m1 = -1e30f, Z0 = 0.f, Z1 = 0.f, T0 = 0.f, T1 = 0.f;

    const uint32_t qrow = (w * 16 + (lane & 15)) * 144 + (lane >> 4) * 16;
    const uint32_t klrow = ((lane & 15)) * 144 + (lane >> 4) * 16;

    const int NB = S_ / 64;
    for (int kb = 0; kb < NB; kb++) {
        const int st = kb & 1;
        const bool more = (kb + 1 < NB);

        // stage K/V(kb) from registers into smem
        attn_stkv(smem, tid, kr, vr);
        // issue M(kb+1) into the other stage
        if (more) {
            attn_cpM(sb, st ^ 1, Mp, q0, (kb + 1) * 64, tid);
            CP_COMMIT();
        }
        if (more) { CP_WAIT1(); } else { CP_WAIT0(); }
        __syncthreads();
        // prefetch K/V(kb+1) into registers — hidden behind the mma below
        if (more) attn_ldkv(Kp, Vp, (kb + 1) * 64, tid, kr, vr);

        // ---- S = Q K^T (3xBF16) ----
        float S[8][4];
#pragma unroll
        for (int t = 0; t < 8; t++)
#pragma unroll
            for (int j = 0; j < 4; j++) S[t][j] = 0.f;
#pragma unroll
        for (int ks = 0; ks < 4; ks++) {
            uint32_t ah[4], al[4];
            ldm4(sb + OQH + qrow + ks * 32, ah);
            ldm4(sb + OQL + qrow + ks * 32, al);
#pragma unroll
            for (int nb = 0; nb < 4; nb++) {
                uint32_t bh4[4], bl4[4];
                ldm4(sb + OKH + klrow + nb * 2304 + ks * 32, bh4);
                ldm4(sb + OKL + klrow + nb * 2304 + ks * 32, bl4);
                uint32_t th0[2] = {bh4[0], bh4[2]}, th1[2] = {bh4[1], bh4[3]};
                uint32_t tl0[2] = {bl4[0], bl4[2]}, tl1[2] = {bl4[1], bl4[3]};
                mma_bf16(S[2 * nb],     ah, th0);
                mma_bf16(S[2 * nb + 1], ah, th1);
                mma_bf16(S[2 * nb],     ah, tl0);
                mma_bf16(S[2 * nb + 1], ah, tl1);
                mma_bf16(S[2 * nb],     al, th0);
                mma_bf16(S[2 * nb + 1], al, th1);
            }
        }

        // ---- masked scale + online softmax (M from stage st) ----
        const unsigned char* msp = smem + OMS + st * MSTG;
        const int mr0 = (w * 16 + qr) * 272 + qc * 8;
        float bm0 = -1e30f, bm1 = -1e30f;
        float mva[8], mvb[8], mvc[8], mvd[8];
#pragma unroll
        for (int t = 0; t < 8; t++) {
            float2 ma = *(const float2*)(msp + mr0 + t * 32);
            float2 mb = *(const float2*)(msp + mr0 + 8 * 272 + t * 32);
            mva[t] = ma.x; mvb[t] = ma.y; mvc[t] = mb.x; mvd[t] = mb.y;
            S[t][0] *= 0.125f * ma.x;
            S[t][1] *= 0.125f * ma.y;
            S[t][2] *= 0.125f * mb.x;
            S[t][3] *= 0.125f * mb.y;
            bm0 = fmaxf(bm0, fmaxf(S[t][0], S[t][1]));
            bm1 = fmaxf(bm1, fmaxf(S[t][2], S[t][3]));
        }
        bm0 = fmaxf(bm0, __shfl_xor_sync(0xffffffffu, bm0, 1));
        bm0 = fmaxf(bm0, __shfl_xor_sync(0xffffffffu, bm0, 2));
        bm1 = fmaxf(bm1, __shfl_xor_sync(0xffffffffu, bm1, 1));
        bm1 = fmaxf(bm1, __shfl_xor_sync(0xffffffffu, bm1, 2));
        float nm0 = fmaxf(m0, bm0), nm1 = fmaxf(m1, bm1);
        float f0 = __expf(m0 - nm0), f1 = __expf(m1 - nm1);
        m0 = nm0; m1 = nm1;
        Z0 *= f0; Z1 *= f1; T0 *= f0; T1 *= f1;
#pragma unroll
        for (int t = 0; t < 8; t++) {
            O[t][0] *= f0; O[t][1] *= f0; O[t][2] *= f1; O[t][3] *= f1;
            float e0 = __expf(S[t][0] - nm0);
            float e1 = __expf(S[t][1] - nm0);
            float e2 = __expf(S[t][2] - nm1);
            float e3 = __expf(S[t][3] - nm1);
            Z0 += e0 + e1; Z1 += e2 + e3;
            float p0 = e0 * mva[t], p1 = e1 * mvb[t];
            float p2 = e2 * mvc[t], p3 = e3 * mvd[t];
            T0 += p0 + p1; T1 += p2 + p3;
            S[t][0] = p0; S[t][1] = p1; S[t][2] = p2; S[t][3] = p3;
        }

        // ---- pack P to bf16 hi/lo A-fragments ----
        uint32_t phi[4][4], plo[4][4];
#pragma unroll
        for (int kt = 0; kt < 4; kt++) {
            unsigned short h0, l0, h1, l1;
            bsplit(S[2 * kt][0], h0, l0); bsplit(S[2 * kt][1], h1, l1);
            phi[kt][0] = (uint32_t)h0 | ((uint32_t)h1 << 16);
            plo[kt][0] = (uint32_t)l0 | ((uint32_t)l1 << 16);
            bsplit(S[2 * kt][2], h0, l0); bsplit(S[2 * kt][3], h1, l1);
            phi[kt][1] = (uint32_t)h0 | ((uint32_t)h1 << 16);
            plo[kt][1] = (uint32_t)l0 | ((uint32_t)l1 << 16);
            bsplit(S[2 * kt + 1][0], h0, l0); bsplit(S[2 * kt + 1][1], h1, l1);
            phi[kt][2] = (uint32_t)h0 | ((uint32_t)h1 << 16);
            plo[kt][2] = (uint32_t)l0 | ((uint32_t)l1 << 16);
            bsplit(S[2 * kt + 1][2], h0, l0); bsplit(S[2 * kt + 1][3], h1, l1);
            phi[kt][3] = (uint32_t)h0 | ((uint32_t)h1 << 16);
            plo[kt][3] = (uint32_t)l0 | ((uint32_t)l1 << 16);
        }

        // ---- O += P @ V ----
#pragma unroll
        for (int kt = 0; kt < 4; kt++) {
#pragma unroll
            for (int nb = 0; nb < 4; nb++) {
                uint32_t vh4[4], vl4[4];
                ldm4(sb + OVH + klrow + nb * 2304 + kt * 32, vh4);
                ldm4(sb + OVL + klrow + nb * 2304 + kt * 32, vl4);
                uint32_t th0[2] = {vh4[0], vh4[2]}, th1[2] = {vh4[1], vh4[3]};
                uint32_t tl0[2] = {vl4[0], vl4[2]}, tl1[2] = {vl4[1], vl4[3]};
                mma_bf16(O[2 * nb],     phi[kt], th0);
                mma_bf16(O[2 * nb + 1], phi[kt], th1);
                mma_bf16(O[2 * nb],     phi[kt], tl0);
                mma_bf16(O[2 * nb + 1], phi[kt], tl1);
                mma_bf16(O[2 * nb],     plo[kt], th0);
                mma_bf16(O[2 * nb + 1], plo[kt], th1);
            }
        }
        __syncthreads();
    }

    // ---- finalize ----
    T0 += __shfl_xor_sync(0xffffffffu, T0, 1);
    T0 += __shfl_xor_sync(0xffffffffu, T0, 2);
    T1 += __shfl_xor_sync(0xffffffffu, T1, 1);
    T1 += __shfl_xor_sync(0xffffffffu, T1, 2);
    Z0 += __shfl_xor_sync(0xffffffffu, Z0, 1);
    Z0 += __shfl_xor_sync(0xffffffffu, Z0, 2);
    Z1 += __shfl_xor_sync(0xffffffffu, Z1, 1);
    Z1 += __shfl_xor_sync(0xffffffffu, Z1, 2);
    float inv0 = 1.0f / (T0 + EPS_ * Z0);
    float inv1 = 1.0f / (T1 + EPS_ * Z1);

    int gr0 = q0 + w * 16 + qr;
#pragma unroll
    for (int t = 0; t < 8; t++) {
        int d = t * 8 + 2 * qc;
        float2 v0 = make_float2(O[t][0] * inv0, O[t][1] * inv0);
        float2 v1 = make_float2(O[t][2] * inv1, O[t][3] * inv1);
        *(float2*)(Out + ((size_t)b * S_ + gr0) * D_ + h * HD_ + d) = v0;
        *(float2*)(Out + ((size_t)b * S_ + gr0 + 8) * D_ + h * HD_ + d) = v1;
    }
}

// ---------------------------------------------------------------------------
// Host
// ---------------------------------------------------------------------------
extern "C" void kernel_launch(void* const* d_in, const int* in_sizes, int n_in,
                              void* d_out, int out_size)
{
    const float* gene = (const float*)d_in[0];
    const float* expr = (const float*)d_in[1];
    const float* Mm   = (const float*)d_in[2];
    const float* Wf   = (const float*)d_in[3];
    const float* bf   = (const float*)d_in[4];
    const float* Wq   = (const float*)d_in[5];
    const float* bq   = (const float*)d_in[6];
    const float* Wk   = (const float*)d_in[7];
    const float* bk   = (const float*)d_in[8];
    const float* Wv   = (const float*)d_in[9];
    const float* bv   = (const float*)d_in[10];
    const float* Wo   = (const float*)d_in[11];
    const float* bo   = (const float*)d_in[12];
    float* out = (float*)d_out;

    float *Qb, *Kb, *Vb, *Ab;
    unsigned short *Fh, *Fl;
    unsigned short *Wfh, *Wfl, *Wqh, *Wql, *Wkh, *Wkl, *Wvh, *Wvl, *Woh, *Wol;
    cudaGetSymbolAddress((void**)&Qb,  g_Q);
    cudaGetSymbolAddress((void**)&Kb,  g_K);
    cudaGetSymbolAddress((void**)&Vb,  g_V);
    cudaGetSymbolAddress((void**)&Ab,  g_attn);
    cudaGetSymbolAddress((void**)&Fh,  g_fus_h);
    cudaGetSymbolAddress((void**)&Fl,  g_fus_l);
    cudaGetSymbolAddress((void**)&Wfh, g_Wf_h);
    cudaGetSymbolAddress((void**)&Wfl, g_Wf_l);
    cudaGetSymbolAddress((void**)&Wqh, g_Wq_h);
    cudaGetSymbolAddress((void**)&Wql, g_Wq_l);
    cudaGetSymbolAddress((void**)&Wkh, g_Wk_h);
    cudaGetSymbolAddress((void**)&Wkl, g_Wk_l);
    cudaGetSymbolAddress((void**)&Wvh, g_Wv_h);
    cudaGetSymbolAddress((void**)&Wvl, g_Wv_l);
    cudaGetSymbolAddress((void**)&Woh, g_Wo_h);
    cudaGetSymbolAddress((void**)&Wol, g_Wo_l);

    cudaFuncSetAttribute(mm_mma<2, 0>, cudaFuncAttributeMaxDynamicSharedMemorySize, GM_SMEM);
    cudaFuncSetAttribute(mm_mma<1, 1>, cudaFuncAttributeMaxDynamicSharedMemorySize, GM_SMEM);
    cudaFuncSetAttribute(mm_mma<1, 0>, cudaFuncAttributeMaxDynamicSharedMemorySize, GM_SMEM);
    cudaFuncSetAttribute(mm_mma<0, 0>, cudaFuncAttributeMaxDynamicSharedMemorySize, GM_SMEM);
    cudaFuncSetAttribute(attn_mma, cudaFuncAttributeMaxDynamicSharedMemorySize, ATTN_SMEM);

    // 1) all weight conversions in ONE launch
    wconv_all<<<dim3(16, 32, 5), dim3(32, 32)>>>(
        Wf, Wq, Wk, Wv, Wo,
        Wfh, Wfl, Wqh, Wql, Wkh, Wkl, Wvh, Wvl, Woh, Wol);

    dim3 gg(D_ / 128, ROWS_ / 128);   // (4, 64)

    // 2) fused = concat(gene, expr) @ Wf + bf  -> bf16 hi/lo only
    mm_mma<2, 0><<<gg, 256, GM_SMEM>>>(gene, expr, D_, D_, D_,
                                       nullptr, nullptr, Wfh, Wfl, bf,
                                       nullptr, Fh, Fl, D_, 2 * D_);
    // 3,4) Q, K from pre-split fused (cp.async A path), head-split epilogue
    mm_mma<1, 1><<<gg, 256, GM_SMEM>>>(nullptr, nullptr, 0, 0, 0,
                                       Fh, Fl, Wqh, Wql, bq,
                                       Qb, nullptr, nullptr, D_, D_);
    mm_mma<1, 1><<<gg, 256, GM_SMEM>>>(nullptr, nullptr, 0, 0, 0,
                                       Fh, Fl, Wkh, Wkl, bk,
                                       Kb, nullptr, nullptr, D_, D_);
    // 5) V from expr (fp32 A path)
    mm_mma<1, 0><<<gg, 256, GM_SMEM>>>(expr, expr, D_, D_, D_,
                                       nullptr, nullptr, Wvh, Wvl, bv,
                                       Vb, nullptr, nullptr, D_, D_);

    // 6) flash attention: 64 q-rows/CTA, 128 threads, 2 CTAs/SM
    attn_mma<<<dim3(S_ / 64, H_, B_), 128, ATTN_SMEM>>>(Qb, Kb, Vb, Mm, Ab);

    // 7) out = attn @ Wo + bo
    mm_mma<0, 0><<<gg, 256, GM_SMEM>>>(Ab, Ab, D_, D_, D_,
                                       nullptr, nullptr, Woh, Wol, bo,
                                       out, nullptr, nullptr, D_, D_);
}

// round 10
// speedup vs baseline: 1.3759x; 1.3759x over previous
#include <cuda_runtime.h>
#include <cuda_bf16.h>
#include <stdint.h>

#define B_   4
#define S_   2048
#define D_   512
#define H_   8
#define HD_  64
#define ROWS_ (B_ * S_)          // 8192
#define EPS_ 1e-8f

// ---------------------------------------------------------------------------
// Scratch (__device__ globals; allocations are forbidden)
// ---------------------------------------------------------------------------
__device__ float g_attn [(size_t)ROWS_ * D_];   // [B,S,D] fp32
// Q/K/V pre-split bf16 hi/lo, [B,H,S,HD]
__device__ unsigned short g_Qh[(size_t)ROWS_ * D_];
__device__ unsigned short g_Ql[(size_t)ROWS_ * D_];
__device__ unsigned short g_Kh[(size_t)ROWS_ * D_];
__device__ unsigned short g_Kl[(size_t)ROWS_ * D_];
__device__ unsigned short g_Vh[(size_t)ROWS_ * D_];
__device__ unsigned short g_Vl[(size_t)ROWS_ * D_];
// fused activations, pre-split bf16 hi/lo
__device__ unsigned short g_fus_h[(size_t)ROWS_ * D_];
__device__ unsigned short g_fus_l[(size_t)ROWS_ * D_];
// Weights transposed to [N][K], split bf16 hi/lo
__device__ unsigned short g_Wf_h[(size_t)D_ * 2 * D_];
__device__ unsigned short g_Wf_l[(size_t)D_ * 2 * D_];
__device__ unsigned short g_Wq_h[(size_t)D_ * D_];
__device__ unsigned short g_Wq_l[(size_t)D_ * D_];
__device__ unsigned short g_Wk_h[(size_t)D_ * D_];
__device__ unsigned short g_Wk_l[(size_t)D_ * D_];
__device__ unsigned short g_Wv_h[(size_t)D_ * D_];
__device__ unsigned short g_Wv_l[(size_t)D_ * D_];
__device__ unsigned short g_Wo_h[(size_t)D_ * D_];
__device__ unsigned short g_Wo_l[(size_t)D_ * D_];

// ---------------------------------------------------------------------------
// sm_80-level PTX helpers (NO tcgen05 — build target is plain sm_103)
// ---------------------------------------------------------------------------
__device__ __forceinline__ uint32_t smem_u32(const void* p) {
    uint32_t a;
    asm("{ .reg .u64 t; cvta.to.shared.u64 t, %1; cvt.u32.u64 %0, t; }"
        : "=r"(a) : "l"(p));
    return a;
}
__device__ __forceinline__ void ldm4(uint32_t addr, uint32_t* r) {
    asm volatile("ldmatrix.sync.aligned.m8n8.x4.shared.b16 {%0,%1,%2,%3}, [%4];"
                 : "=r"(r[0]), "=r"(r[1]), "=r"(r[2]), "=r"(r[3]) : "r"(addr));
}
__device__ __forceinline__ void ldm4t(uint32_t addr, uint32_t* r) {
    asm volatile("ldmatrix.sync.aligned.m8n8.x4.trans.shared.b16 {%0,%1,%2,%3}, [%4];"
                 : "=r"(r[0]), "=r"(r[1]), "=r"(r[2]), "=r"(r[3]) : "r"(addr));
}
__device__ __forceinline__ void mma_bf16(float* c, const uint32_t* a,
                                         const uint32_t* b) {
    asm volatile("mma.sync.aligned.m16n8k16.row.col.f32.bf16.bf16.f32 "
                 "{%0,%1,%2,%3}, {%4,%5,%6,%7}, {%8,%9}, {%0,%1,%2,%3};"
                 : "+f"(c[0]), "+f"(c[1]), "+f"(c[2]), "+f"(c[3])
                 : "r"(a[0]), "r"(a[1]), "r"(a[2]), "r"(a[3]),
                   "r"(b[0]), "r"(b[1]));
}
#define CP_ASYNC16(dst, src) \
    asm volatile("cp.async.ca.shared.global [%0], [%1], 16;" \
                 :: "r"(dst), "l"(src))
#define CP_COMMIT() asm volatile("cp.async.commit_group;" ::: "memory")
#define CP_WAIT0()  asm volatile("cp.async.wait_group 0;" ::: "memory")
#define CP_WAIT1()  asm volatile("cp.async.wait_group 1;" ::: "memory")

__device__ __forceinline__ void bsplit(float v, unsigned short& h,
                                       unsigned short& l) {
    __nv_bfloat16 hb = __float2bfloat16(v);
    float r = v - __bfloat162float(hb);
    __nv_bfloat16 lb = __float2bfloat16(r);
    h = __bfloat16_as_ushort(hb);
    l = __bfloat16_as_ushort(lb);
}

// ---------------------------------------------------------------------------
// Batched weight preconvert (ONE launch): W[K][N] -> Wt[N][K] bf16 hi/lo
// ---------------------------------------------------------------------------
__global__ void wconv_all(
    const float* __restrict__ Wf, const float* __restrict__ Wq,
    const float* __restrict__ Wk, const float* __restrict__ Wv,
    const float* __restrict__ Wo,
    unsigned short* __restrict__ Wfh, unsigned short* __restrict__ Wfl,
    unsigned short* __restrict__ Wqh, unsigned short* __restrict__ Wql,
    unsigned short* __restrict__ Wkh, unsigned short* __restrict__ Wkl,
    unsigned short* __restrict__ Wvh, unsigned short* __restrict__ Wvl,
    unsigned short* __restrict__ Woh, unsigned short* __restrict__ Wol)
{
    const float* W; unsigned short *Th, *Tl; int K;
    switch (blockIdx.z) {
        case 0:  W = Wf; Th = Wfh; Tl = Wfl; K = 1024; break;
        case 1:  W = Wq; Th = Wqh; Tl = Wql; K = 512;  break;
        case 2:  W = Wk; Th = Wkh; Tl = Wkl; K = 512;  break;
        case 3:  W = Wv; Th = Wvh; Tl = Wvl; K = 512;  break;
        default: W = Wo; Th = Woh; Tl = Wol; K = 512;  break;
    }
    int k0 = blockIdx.y * 32, n0 = blockIdx.x * 32;
    if (k0 >= K) return;
    __shared__ float t[32][33];
    int tx = threadIdx.x, ty = threadIdx.y;
    t[ty][tx] = W[(size_t)(k0 + ty) * D_ + n0 + tx];
    __syncthreads();
    float v = t[tx][ty];                 // W[k0+tx][n0+ty]
    unsigned short h, l;
    bsplit(v, h, l);
    size_t o = (size_t)(n0 + ty) * K + k0 + tx;
    Th[o] = h;
    Tl[o] = l;
}

// ---------------------------------------------------------------------------
// 3xBF16 tensor-core GEMM: C[M,N] = A[M,K] @ W[K,N] + bias
// CTA 128x128, K-chunk 32, 8 warps (2x4) of 64x32, 2-stage cp.async pipeline.
// ASRC 0: A fp32 (two sources, K-split), inline bsplit + STS.
// ASRC 1: A pre-split bf16 hi/lo [M][K] via cp.async.
// MODE 0: C fp32 row-major.  MODE 2: bf16 hi/lo row-major.
// MODE 3: bf16 hi/lo head-split scatter to [B,H,S,HD].
// ---------------------------------------------------------------------------
#define GSTAGE   40960
#define GOFF_AH  0
#define GOFF_AL  10240
#define GOFF_BH  20480
#define GOFF_BL  30720
#define GM_SMEM  (2 * GSTAGE)

__device__ __forceinline__ void gemm_ldA(const float* A0, const float* A1,
                                         int sA0, int sA1, int Ksplit,
                                         int bm, int k0, int tid, float4* av)
{
#pragma unroll
    for (int i = 0; i < 4; i++) {
        int fid = tid + i * 256;
        int m = fid >> 3, kq = fid & 7;
        int kg = k0 + kq * 4;
        const float* src = (kg < Ksplit)
            ? A0 + (size_t)(bm + m) * sA0 + kg
            : A1 + (size_t)(bm + m) * sA1 + (kg - Ksplit);
        av[i] = *(const float4*)src;
    }
}
__device__ __forceinline__ void gemm_stA(unsigned char* stage, int tid,
                                         const float4* av)
{
#pragma unroll
    for (int i = 0; i < 4; i++) {
        int fid = tid + i * 256;
        int m = fid >> 3, kq = fid & 7;
        ushort4 h, l;
        bsplit(av[i].x, h.x, l.x);
        bsplit(av[i].y, h.y, l.y);
        bsplit(av[i].z, h.z, l.z);
        bsplit(av[i].w, h.w, l.w);
        *(ushort4*)(stage + GOFF_AH + m * 80 + kq * 8) = h;
        *(ushort4*)(stage + GOFF_AL + m * 80 + kq * 8) = l;
    }
}
__device__ __forceinline__ void gemm_cpPre(uint32_t stage_u32,
                                           uint32_t offH, uint32_t offL,
                                           const unsigned short* Th,
                                           const unsigned short* Tl,
                                           int row0, int K, int k0, int tid)
{
#pragma unroll
    for (int i = 0; i < 2; i++) {
        int fid = tid + i * 256;
        int r = fid >> 2, c16 = fid & 3;
        size_t gs = (size_t)(row0 + r) * K + k0 + c16 * 8;
        CP_ASYNC16(stage_u32 + offH + r * 80 + c16 * 16, (const char*)(Th + gs));
        CP_ASYNC16(stage_u32 + offL + r * 80 + c16 * 16, (const char*)(Tl + gs));
    }
}

template <int MODE, int ASRC>
__global__ __launch_bounds__(256, 2) void mm_mma(
    const float* __restrict__ A0, const float* __restrict__ A1,
    int sA0, int sA1, int Ksplit,
    const unsigned short* __restrict__ Ah, const unsigned short* __restrict__ Al,
    const unsigned short* __restrict__ Bh, const unsigned short* __restrict__ Bl,
    const float* __restrict__ bias, float* __restrict__ C,
    unsigned short* __restrict__ Ch, unsigned short* __restrict__ Cl,
    int N, int K)
{
    extern __shared__ __align__(16) unsigned char smem[];
    const uint32_t sb = smem_u32(smem);
    const int tid = threadIdx.x, lane = tid & 31, wid = tid >> 5;
    const int wy = wid >> 2, wx = wid & 3;
    const int bn = blockIdx.x * 128, bm = blockIdx.y * 128;
    const int NC = K / 32;

    float acc[4][4][4];
#pragma unroll
    for (int i = 0; i < 4; i++)
#pragma unroll
        for (int j = 0; j < 4; j++)
#pragma unroll
            for (int q = 0; q < 4; q++) acc[i][j][q] = 0.f;

    const uint32_t arow = (wy * 64 + (lane & 15)) * 80 + (lane >> 4) * 16;
    const uint32_t brow = (wx * 32 + (lane & 15)) * 80 + (lane >> 4) * 16;

    float4 av[4];
    if (ASRC == 0) {
        gemm_ldA(A0, A1, sA0, sA1, Ksplit, bm, 0, tid, av);
        gemm_cpPre(sb, GOFF_BH, GOFF_BL, Bh, Bl, bn, K, 0, tid);
        CP_COMMIT();
        gemm_stA(smem, tid, av);
    } else {
        gemm_cpPre(sb, GOFF_AH, GOFF_AL, Ah, Al, bm, K, 0, tid);
        gemm_cpPre(sb, GOFF_BH, GOFF_BL, Bh, Bl, bn, K, 0, tid);
        CP_COMMIT();
    }

    for (int c = 0; c < NC; c++) {
        const int st = c & 1;
        const bool more = (c + 1 < NC);
        if (more) {
            uint32_t s1 = sb + ((c + 1) & 1) * GSTAGE;
            if (ASRC == 0) {
                gemm_ldA(A0, A1, sA0, sA1, Ksplit, bm, (c + 1) * 32, tid, av);
            } else {
                gemm_cpPre(s1, GOFF_AH, GOFF_AL, Ah, Al, bm, K, (c + 1) * 32, tid);
            }
            gemm_cpPre(s1, GOFF_BH, GOFF_BL, Bh, Bl, bn, K, (c + 1) * 32, tid);
            CP_COMMIT();
        }
        if (more) { CP_WAIT1(); } else { CP_WAIT0(); }
        __syncthreads();

        const uint32_t s0 = sb + st * GSTAGE;
#pragma unroll
        for (int ks = 0; ks < 2; ks++) {
            uint32_t ah[4][4], al[4][4];
#pragma unroll
            for (int mt = 0; mt < 4; mt++) {
                ldm4(s0 + GOFF_AH + arow + mt * 1280 + ks * 32, ah[mt]);
                ldm4(s0 + GOFF_AL + arow + mt * 1280 + ks * 32, al[mt]);
            }
#pragma unroll
            for (int nb = 0; nb < 2; nb++) {
                uint32_t bh4[4], bl4[4];
                ldm4(s0 + GOFF_BH + brow + nb * 1280 + ks * 32, bh4);
                ldm4(s0 + GOFF_BL + brow + nb * 1280 + ks * 32, bl4);
                uint32_t th0[2] = {bh4[0], bh4[2]}, th1[2] = {bh4[1], bh4[3]};
                uint32_t tl0[2] = {bl4[0], bl4[2]}, tl1[2] = {bl4[1], bl4[3]};
#pragma unroll
                for (int mt = 0; mt < 4; mt++) {
                    mma_bf16(acc[mt][2 * nb],     ah[mt], th0);
                    mma_bf16(acc[mt][2 * nb + 1], ah[mt], th1);
                    mma_bf16(acc[mt][2 * nb],     ah[mt], tl0);
                    mma_bf16(acc[mt][2 * nb + 1], ah[mt], tl1);
                    mma_bf16(acc[mt][2 * nb],     al[mt], th0);
                    mma_bf16(acc[mt][2 * nb + 1], al[mt], th1);
                }
            }
        }
        if (ASRC == 0 && more) gemm_stA(smem + ((c + 1) & 1) * GSTAGE, tid, av);
        __syncthreads();
    }

    // epilogue
#pragma unroll
    for (int mt = 0; mt < 4; mt++) {
#pragma unroll
        for (int nt = 0; nt < 4; nt++) {
            int r0 = bm + wy * 64 + mt * 16 + (lane >> 2);
            int col = bn + wx * 32 + nt * 8 + 2 * (lane & 3);
            float b0 = bias[col], b1 = bias[col + 1];
            float2 v0 = make_float2(acc[mt][nt][0] + b0, acc[mt][nt][1] + b1);
            float2 v1 = make_float2(acc[mt][nt][2] + b0, acc[mt][nt][3] + b1);
            if (MODE == 0) {
                *(float2*)(C + (size_t)r0 * N + col) = v0;
                *(float2*)(C + (size_t)(r0 + 8) * N + col) = v1;
            } else if (MODE == 2) {
                unsigned short hx, lx, hy, ly;
                bsplit(v0.x, hx, lx); bsplit(v0.y, hy, ly);
                *(ushort2*)(Ch + (size_t)r0 * N + col) = make_ushort2(hx, hy);
                *(ushort2*)(Cl + (size_t)r0 * N + col) = make_ushort2(lx, ly);
                bsplit(v1.x, hx, lx); bsplit(v1.y, hy, ly);
                *(ushort2*)(Ch + (size_t)(r0 + 8) * N + col) = make_ushort2(hx, hy);
                *(ushort2*)(Cl + (size_t)(r0 + 8) * N + col) = make_ushort2(lx, ly);
            } else {   // MODE 3: head-split bf16 hi/lo
                int hh = col >> 6, dd = col & (HD_ - 1);
                int bb0 = r0 >> 11, ss0 = r0 & (S_ - 1);
                size_t o0 = (((size_t)bb0 * H_ + hh) * S_ + ss0) * HD_ + dd;
                unsigned short hx, lx, hy, ly;
                bsplit(v0.x, hx, lx); bsplit(v0.y, hy, ly);
                *(ushort2*)(Ch + o0) = make_ushort2(hx, hy);
                *(ushort2*)(Cl + o0) = make_ushort2(lx, ly);
                int r1 = r0 + 8;
                int bb1 = r1 >> 11, ss1 = r1 & (S_ - 1);
                size_t o1 = (((size_t)bb1 * H_ + hh) * S_ + ss1) * HD_ + dd;
                bsplit(v1.x, hx, lx); bsplit(v1.y, hy, ly);
                *(ushort2*)(Ch + o1) = make_ushort2(hx, hy);
                *(ushort2*)(Cl + o1) = make_ushort2(lx, ly);
            }
        }
    }
}

// ---------------------------------------------------------------------------
// Tensor-core flash attention, masked softmax + L1 renorm.
// CTA: 128 q-rows x one (b,h); 256 threads = 8 warps x 16 rows; 64-key blocks.
// ALL inputs pre-split bf16 hi/lo, loaded purely via cp.async.
// K/V/M double-buffered (2 stages); V consumed via ldmatrix.trans (no smem
// transpose). Inner loop = ldmatrix + HMMA + softmax only.
// ---------------------------------------------------------------------------
#define AQ_H 0
#define AQ_L 18432
#define ASTG_BASE 36864
#define ASTG  73728
#define AS_KH 0
#define AS_KL 9216
#define AS_VH 18432
#define AS_VL 27648
#define AS_M  36864
#define ATTN_SMEM (36864 + 2 * 73728)   // 184320

__device__ __forceinline__ void attn_cp_stage(
    uint32_t sb, int s,
    const unsigned short* Kh, const unsigned short* Kl,
    const unsigned short* Vh, const unsigned short* Vl,
    const float* Mp, size_t bhS, int q0, int kk0, int tid)
{
    const uint32_t base = sb + ASTG_BASE + s * ASTG;
    // K/V: 4 tiles x 64 rows x 8 chunks (16B); t uniform per i
#pragma unroll
    for (int i = 0; i < 8; i++) {
        const int t = i >> 1;
        const int idx = tid + (i & 1) * 256;
        const int row = idx >> 3, c16 = idx & 7;
        const unsigned short* sp = (t == 0) ? Kh : (t == 1) ? Kl
                                 : (t == 2) ? Vh : Vl;
        CP_ASYNC16(base + t * 9216 + row * 144 + c16 * 16,
                   (const char*)(sp + (bhS + kk0 + row) * HD_ + c16 * 8));
    }
    // M: 128 rows x 16 chunks, pitch 288
#pragma unroll
    for (int i = 0; i < 8; i++) {
        const int idx = tid + i * 256;
        const int row = idx >> 4, c16 = idx & 15;
        CP_ASYNC16(base + AS_M + row * 288 + c16 * 16,
                   (const char*)(Mp + (size_t)(q0 + row) * S_ + kk0 + c16 * 4));
    }
}

__global__ __launch_bounds__(256, 1) void attn_mma(
    const unsigned short* __restrict__ Qh, const unsigned short* __restrict__ Ql,
    const unsigned short* __restrict__ Kh, const unsigned short* __restrict__ Kl,
    const unsigned short* __restrict__ Vh, const unsigned short* __restrict__ Vl,
    const float* __restrict__ Mm, float* __restrict__ Out)
{
    extern __shared__ __align__(16) unsigned char smem[];
    const uint32_t sb = smem_u32(smem);

    const int q0 = blockIdx.x * 128;
    const int h  = blockIdx.y;
    const int b  = blockIdx.z;
    const int tid = threadIdx.x, lane = tid & 31, w = tid >> 5;
    const int qr = lane >> 2, qc = lane & 3;

    const size_t bhS = ((size_t)b * H_ + h) * S_;
    const float* Mp = Mm + (size_t)b * S_ * S_;

    // prologue: Q tile + stage 0 (K/V/M) via cp.async, one group
#pragma unroll
    for (int i = 0; i < 8; i++) {
        const int idx = tid + (i & 3) * 256;
        const int row = idx >> 3, c16 = idx & 7;
        const unsigned short* sp = (i < 4) ? Qh : Ql;
        const uint32_t off = (i < 4) ? AQ_H : AQ_L;
        CP_ASYNC16(sb + off + row * 144 + c16 * 16,
                   (const char*)(sp + (bhS + q0 + row) * HD_ + c16 * 8));
    }
    attn_cp_stage(sb, 0, Kh, Kl, Vh, Vl, Mp, bhS, q0, 0, tid);
    CP_COMMIT();

    float O[8][4];
#pragma unroll
    for (int t = 0; t < 8; t++)
#pragma unroll
        for (int j = 0; j < 4; j++) O[t][j] = 0.f;
    float m0 = -1e30f, m1 = -1e30f, Z0 = 0.f, Z1 = 0.f, T0 = 0.f, T1 = 0.f;

    const uint32_t qrow = (w * 16 + (lane & 15)) * 144 + (lane >> 4) * 16;
    const uint32_t klrow = (lane & 15) * 144 + (lane >> 4) * 16;

    const int NB = S_ / 64;
    for (int kb = 0; kb < NB; kb++) {
        const int st = kb & 1;
        const bool more = (kb + 1 < NB);
        if (more) {
            attn_cp_stage(sb, st ^ 1, Kh, Kl, Vh, Vl, Mp, bhS, q0,
                          (kb + 1) * 64, tid);
            CP_COMMIT();
            CP_WAIT1();
        } else {
            CP_WAIT0();
        }
        __syncthreads();

        const uint32_t stg = sb + ASTG_BASE + st * ASTG;

        // ---- S = Q K^T (3xBF16) ----
        float S[8][4];
#pragma unroll
        for (int t = 0; t < 8; t++)
#pragma unroll
            for (int j = 0; j < 4; j++) S[t][j] = 0.f;
#pragma unroll
        for (int ks = 0; ks < 4; ks++) {
            uint32_t ah[4], al[4];
            ldm4(sb + AQ_H + qrow + ks * 32, ah);
            ldm4(sb + AQ_L + qrow + ks * 32, al);
#pragma unroll
            for (int nb = 0; nb < 4; nb++) {
                uint32_t bh4[4], bl4[4];
                ldm4(stg + AS_KH + klrow + nb * 2304 + ks * 32, bh4);
                ldm4(stg + AS_KL + klrow + nb * 2304 + ks * 32, bl4);
                uint32_t th0[2] = {bh4[0], bh4[2]}, th1[2] = {bh4[1], bh4[3]};
                uint32_t tl0[2] = {bl4[0], bl4[2]}, tl1[2] = {bl4[1], bl4[3]};
                mma_bf16(S[2 * nb],     ah, th0);
                mma_bf16(S[2 * nb + 1], ah, th1);
                mma_bf16(S[2 * nb],     ah, tl0);
                mma_bf16(S[2 * nb + 1], ah, tl1);
                mma_bf16(S[2 * nb],     al, th0);
                mma_bf16(S[2 * nb + 1], al, th1);
            }
        }

        // ---- masked scale + online softmax (M from stage st, pitch 288) ----
        const unsigned char* msp = smem + ASTG_BASE + st * ASTG + AS_M;
        const int mr0 = (w * 16 + qr) * 288 + qc * 8;
        float bm0 = -1e30f, bm1 = -1e30f;
        float mva[8], mvb[8], mvc[8], mvd[8];
#pragma unroll
        for (int t = 0; t < 8; t++) {
            float2 ma = *(const float2*)(msp + mr0 + t * 32);
            float2 mb = *(const float2*)(msp + mr0 + 8 * 288 + t * 32);
            mva[t] = ma.x; mvb[t] = ma.y; mvc[t] = mb.x; mvd[t] = mb.y;
            S[t][0] *= 0.125f * ma.x;
            S[t][1] *= 0.125f * ma.y;
            S[t][2] *= 0.125f * mb.x;
            S[t][3] *= 0.125f * mb.y;
            bm0 = fmaxf(bm0, fmaxf(S[t][0], S[t][1]));
            bm1 = fmaxf(bm1, fmaxf(S[t][2], S[t][3]));
        }
        bm0 = fmaxf(bm0, __shfl_xor_sync(0xffffffffu, bm0, 1));
        bm0 = fmaxf(bm0, __shfl_xor_sync(0xffffffffu, bm0, 2));
        bm1 = fmaxf(bm1, __shfl_xor_sync(0xffffffffu, bm1, 1));
        bm1 = fmaxf(bm1, __shfl_xor_sync(0xffffffffu, bm1, 2));
        float nm0 = fmaxf(m0, bm0), nm1 = fmaxf(m1, bm1);
        float f0 = __expf(m0 - nm0), f1 = __expf(m1 - nm1);
        m0 = nm0; m1 = nm1;
        Z0 *= f0; Z1 *= f1; T0 *= f0; T1 *= f1;
#pragma unroll
        for (int t = 0; t < 8; t++) {
            O[t][0] *= f0; O[t][1] *= f0; O[t][2] *= f1; O[t][3] *= f1;
            float e0 = __expf(S[t][0] - nm0);
            float e1 = __expf(S[t][1] - nm0);
            float e2 = __expf(S[t][2] - nm1);
            float e3 = __expf(S[t][3] - nm1);
            Z0 += e0 + e1; Z1 += e2 + e3;
            float p0 = e0 * mva[t], p1 = e1 * mvb[t];
            float p2 = e2 * mvc[t], p3 = e3 * mvd[t];
            T0 += p0 + p1; T1 += p2 + p3;
            S[t][0] = p0; S[t][1] = p1; S[t][2] = p2; S[t][3] = p3;
        }

        // ---- pack P to bf16 hi/lo A-fragments ----
        uint32_t phi[4][4], plo[4][4];
#pragma unroll
        for (int kt = 0; kt < 4; kt++) {
            unsigned short h0, l0, h1, l1;
            bsplit(S[2 * kt][0], h0, l0); bsplit(S[2 * kt][1], h1, l1);
            phi[kt][0] = (uint32_t)h0 | ((uint32_t)h1 << 16);
            plo[kt][0] = (uint32_t)l0 | ((uint32_t)l1 << 16);
            bsplit(S[2 * kt][2], h0, l0); bsplit(S[2 * kt][3], h1, l1);
            phi[kt][1] = (uint32_t)h0 | ((uint32_t)h1 << 16);
            plo[kt][1] = (uint32_t)l0 | ((uint32_t)l1 << 16);
            bsplit(S[2 * kt + 1][0], h0, l0); bsplit(S[2 * kt + 1][1], h1, l1);
            phi[kt][2] = (uint32_t)h0 | ((uint32_t)h1 << 16);
            plo[kt][2] = (uint32_t)l0 | ((uint32_t)l1 << 16);
            bsplit(S[2 * kt + 1][2], h0, l0); bsplit(S[2 * kt + 1][3], h1, l1);
            phi[kt][3] = (uint32_t)h0 | ((uint32_t)h1 << 16);
            plo[kt][3] = (uint32_t)l0 | ((uint32_t)l1 << 16);
        }

        // ---- O += P @ V  (V via ldmatrix.trans on [key][d] tile) ----
#pragma unroll
        for (int kt = 0; kt < 4; kt++) {
#pragma unroll
            for (int nb = 0; nb < 4; nb++) {
                uint32_t vh4[4], vl4[4];
                ldm4t(stg + AS_VH + kt * 2304 + klrow + nb * 32, vh4);
                ldm4t(stg + AS_VL + kt * 2304 + klrow + nb * 32, vl4);
                uint32_t th0[2] = {vh4[0], vh4[1]}, th1[2] = {vh4[2], vh4[3]};
                uint32_t tl0[2] = {vl4[0], vl4[1]}, tl1[2] = {vl4[2], vl4[3]};
                mma_bf16(O[2 * nb],     phi[kt], th0);
                mma_bf16(O[2 * nb + 1], phi[kt], th1);
                mma_bf16(O[2 * nb],     phi[kt], tl0);
                mma_bf16(O[2 * nb + 1], phi[kt], tl1);
                mma_bf16(O[2 * nb],     plo[kt], th0);
                mma_bf16(O[2 * nb + 1], plo[kt], th1);
            }
        }
        __syncthreads();
    }

    // ---- finalize ----
    T0 += __shfl_xor_sync(0xffffffffu, T0, 1);
    T0 += __shfl_xor_sync(0xffffffffu, T0, 2);
    T1 += __shfl_xor_sync(0xffffffffu, T1, 1);
    T1 += __shfl_xor_sync(0xffffffffu, T1, 2);
    Z0 += __shfl_xor_sync(0xffffffffu, Z0, 1);
    Z0 += __shfl_xor_sync(0xffffffffu, Z0, 2);
    Z1 += __shfl_xor_sync(0xffffffffu, Z1, 1);
    Z1 += __shfl_xor_sync(0xffffffffu, Z1, 2);
    float inv0 = 1.0f / (T0 + EPS_ * Z0);
    float inv1 = 1.0f / (T1 + EPS_ * Z1);

    int gr0 = q0 + w * 16 + qr;
#pragma unroll
    for (int t = 0; t < 8; t++) {
        int d = t * 8 + 2 * qc;
        float2 v0 = make_float2(O[t][0] * inv0, O[t][1] * inv0);
        float2 v1 = make_float2(O[t][2] * inv1, O[t][3] * inv1);
        *(float2*)(Out + ((size_t)b * S_ + gr0) * D_ + h * HD_ + d) = v0;
        *(float2*)(Out + ((size_t)b * S_ + gr0 + 8) * D_ + h * HD_ + d) = v1;
    }
}

// ---------------------------------------------------------------------------
// Host
// ---------------------------------------------------------------------------
extern "C" void kernel_launch(void* const* d_in, const int* in_sizes, int n_in,
                              void* d_out, int out_size)
{
    const float* gene = (const float*)d_in[0];
    const float* expr = (const float*)d_in[1];
    const float* Mm   = (const float*)d_in[2];
    const float* Wf   = (const float*)d_in[3];
    const float* bf   = (const float*)d_in[4];
    const float* Wq   = (const float*)d_in[5];
    const float* bq   = (const float*)d_in[6];
    const float* Wk   = (const float*)d_in[7];
    const float* bk   = (const float*)d_in[8];
    const float* Wv   = (const float*)d_in[9];
    const float* bv   = (const float*)d_in[10];
    const float* Wo   = (const float*)d_in[11];
    const float* bo   = (const float*)d_in[12];
    float* out = (float*)d_out;

    float* Ab;
    unsigned short *Qh, *Ql, *Kh, *Kl, *Vh, *Vl, *Fh, *Fl;
    unsigned short *Wfh, *Wfl, *Wqh, *Wql, *Wkh, *Wkl, *Wvh, *Wvl, *Woh, *Wol;
    cudaGetSymbolAddress((void**)&Ab,  g_attn);
    cudaGetSymbolAddress((void**)&Qh,  g_Qh);
    cudaGetSymbolAddress((void**)&Ql,  g_Ql);
    cudaGetSymbolAddress((void**)&Kh,  g_Kh);
    cudaGetSymbolAddress((void**)&Kl,  g_Kl);
    cudaGetSymbolAddress((void**)&Vh,  g_Vh);
    cudaGetSymbolAddress((void**)&Vl,  g_Vl);
    cudaGetSymbolAddress((void**)&Fh,  g_fus_h);
    cudaGetSymbolAddress((void**)&Fl,  g_fus_l);
    cudaGetSymbolAddress((void**)&Wfh, g_Wf_h);
    cudaGetSymbolAddress((void**)&Wfl, g_Wf_l);
    cudaGetSymbolAddress((void**)&Wqh, g_Wq_h);
    cudaGetSymbolAddress((void**)&Wql, g_Wq_l);
    cudaGetSymbolAddress((void**)&Wkh, g_Wk_h);
    cudaGetSymbolAddress((void**)&Wkl, g_Wk_l);
    cudaGetSymbolAddress((void**)&Wvh, g_Wv_h);
    cudaGetSymbolAddress((void**)&Wvl, g_Wv_l);
    cudaGetSymbolAddress((void**)&Woh, g_Wo_h);
    cudaGetSymbolAddress((void**)&Wol, g_Wo_l);

    cudaFuncSetAttribute(mm_mma<2, 0>, cudaFuncAttributeMaxDynamicSharedMemorySize, GM_SMEM);
    cudaFuncSetAttribute(mm_mma<3, 1>, cudaFuncAttributeMaxDynamicSharedMemorySize, GM_SMEM);
    cudaFuncSetAttribute(mm_mma<3, 0>, cudaFuncAttributeMaxDynamicSharedMemorySize, GM_SMEM);
    cudaFuncSetAttribute(mm_mma<0, 0>, cudaFuncAttributeMaxDynamicSharedMemorySize, GM_SMEM);
    cudaFuncSetAttribute(attn_mma, cudaFuncAttributeMaxDynamicSharedMemorySize, ATTN_SMEM);

    // 1) all weight conversions in ONE launch
    wconv_all<<<dim3(16, 32, 5), dim3(32, 32)>>>(
        Wf, Wq, Wk, Wv, Wo,
        Wfh, Wfl, Wqh, Wql, Wkh, Wkl, Wvh, Wvl, Woh, Wol);

    dim3 gg(D_ / 128, ROWS_ / 128);   // (4, 64)

    // 2) fused = concat(gene, expr) @ Wf + bf  -> bf16 hi/lo row-major
    mm_mma<2, 0><<<gg, 256, GM_SMEM>>>(gene, expr, D_, D_, D_,
                                       nullptr, nullptr, Wfh, Wfl, bf,
                                       nullptr, Fh, Fl, D_, 2 * D_);
    // 3,4) Q, K from pre-split fused -> head-split bf16 hi/lo
    mm_mma<3, 1><<<gg, 256, GM_SMEM>>>(nullptr, nullptr, 0, 0, 0,
                                       Fh, Fl, Wqh, Wql, bq,
                                       nullptr, Qh, Ql, D_, D_);
    mm_mma<3, 1><<<gg, 256, GM_SMEM>>>(nullptr, nullptr, 0, 0, 0,
                                       Fh, Fl, Wkh, Wkl, bk,
                                       nullptr, Kh, Kl, D_, D_);
    // 5) V from expr (fp32 A path) -> head-split bf16 hi/lo
    mm_mma<3, 0><<<gg, 256, GM_SMEM>>>(expr, expr, D_, D_, D_,
                                       nullptr, nullptr, Wvh, Wvl, bv,
                                       nullptr, Vh, Vl, D_, D_);

    // 6) flash attention: pure cp.async pipeline, pre-split inputs
    attn_mma<<<dim3(S_ / 128, H_, B_), 256, ATTN_SMEM>>>(Qh, Ql, Kh, Kl,
                                                         Vh, Vl, Mm, Ab);

    // 7) out = attn @ Wo + bo
    mm_mma<0, 0><<<gg, 256, GM_SMEM>>>(Ab, Ab, D_, D_, D_,
                                       nullptr, nullptr, Woh, Wol, bo,
                                       out, nullptr, nullptr, D_, D_);
}

// round 11
// speedup vs baseline: 1.4007x; 1.0180x over previous
#include <cuda_runtime.h>
#include <cuda_bf16.h>
#include <stdint.h>

#define B_   4
#define S_   2048
#define D_   512
#define H_   8
#define HD_  64
#define ROWS_ (B_ * S_)          // 8192
#define EPS_ 1e-8f

// ---------------------------------------------------------------------------
// Scratch (__device__ globals; allocations are forbidden)
// ---------------------------------------------------------------------------
__device__ float g_attn [(size_t)ROWS_ * D_];   // [B,S,D] fp32
// Q/K/V pre-split bf16 hi/lo, [B,H,S,HD]  (Q pre-scaled by 0.125)
__device__ unsigned short g_Qh[(size_t)ROWS_ * D_];
__device__ unsigned short g_Ql[(size_t)ROWS_ * D_];
__device__ unsigned short g_Kh[(size_t)ROWS_ * D_];
__device__ unsigned short g_Kl[(size_t)ROWS_ * D_];
__device__ unsigned short g_Vh[(size_t)ROWS_ * D_];
__device__ unsigned short g_Vl[(size_t)ROWS_ * D_];
// fused activations, pre-split bf16 hi/lo
__device__ unsigned short g_fus_h[(size_t)ROWS_ * D_];
__device__ unsigned short g_fus_l[(size_t)ROWS_ * D_];
// Weights transposed to [N][K], split bf16 hi/lo
__device__ unsigned short g_Wf_h[(size_t)D_ * 2 * D_];
__device__ unsigned short g_Wf_l[(size_t)D_ * 2 * D_];
__device__ unsigned short g_Wq_h[(size_t)D_ * D_];
__device__ unsigned short g_Wq_l[(size_t)D_ * D_];
__device__ unsigned short g_Wk_h[(size_t)D_ * D_];
__device__ unsigned short g_Wk_l[(size_t)D_ * D_];
__device__ unsigned short g_Wv_h[(size_t)D_ * D_];
__device__ unsigned short g_Wv_l[(size_t)D_ * D_];
__device__ unsigned short g_Wo_h[(size_t)D_ * D_];
__device__ unsigned short g_Wo_l[(size_t)D_ * D_];

// ---------------------------------------------------------------------------
// sm_80-level PTX helpers (NO tcgen05 — build target is plain sm_103)
// ---------------------------------------------------------------------------
__device__ __forceinline__ uint32_t smem_u32(const void* p) {
    uint32_t a;
    asm("{ .reg .u64 t; cvta.to.shared.u64 t, %1; cvt.u32.u64 %0, t; }"
        : "=r"(a) : "l"(p));
    return a;
}
__device__ __forceinline__ void ldm4(uint32_t addr, uint32_t* r) {
    asm volatile("ldmatrix.sync.aligned.m8n8.x4.shared.b16 {%0,%1,%2,%3}, [%4];"
                 : "=r"(r[0]), "=r"(r[1]), "=r"(r[2]), "=r"(r[3]) : "r"(addr));
}
__device__ __forceinline__ void ldm4t(uint32_t addr, uint32_t* r) {
    asm volatile("ldmatrix.sync.aligned.m8n8.x4.trans.shared.b16 {%0,%1,%2,%3}, [%4];"
                 : "=r"(r[0]), "=r"(r[1]), "=r"(r[2]), "=r"(r[3]) : "r"(addr));
}
__device__ __forceinline__ void mma_bf16(float* c, const uint32_t* a,
                                         const uint32_t* b) {
    asm volatile("mma.sync.aligned.m16n8k16.row.col.f32.bf16.bf16.f32 "
                 "{%0,%1,%2,%3}, {%4,%5,%6,%7}, {%8,%9}, {%0,%1,%2,%3};"
                 : "+f"(c[0]), "+f"(c[1]), "+f"(c[2]), "+f"(c[3])
                 : "r"(a[0]), "r"(a[1]), "r"(a[2]), "r"(a[3]),
                   "r"(b[0]), "r"(b[1]));
}
#define CP_ASYNC16(dst, src) \
    asm volatile("cp.async.ca.shared.global [%0], [%1], 16;" \
                 :: "r"(dst), "l"(src))
#define CP_COMMIT() asm volatile("cp.async.commit_group;" ::: "memory")
#define CP_WAIT0()  asm volatile("cp.async.wait_group 0;" ::: "memory")
#define CP_WAIT1()  asm volatile("cp.async.wait_group 1;" ::: "memory")

__device__ __forceinline__ void bsplit(float v, unsigned short& h,
                                       unsigned short& l) {
    __nv_bfloat16 hb = __float2bfloat16(v);
    float r = v - __bfloat162float(hb);
    __nv_bfloat16 lb = __float2bfloat16(r);
    h = __bfloat16_as_ushort(hb);
    l = __bfloat16_as_ushort(lb);
}
// packed hi/lo split of a float pair into bf16x2 fragment words
// (element0 in low half, element1 in high half; RN rounding == bsplit)
__device__ __forceinline__ void pack2(float f0, float f1,
                                      uint32_t& hi2, uint32_t& lo2) {
    uint32_t h;
    asm("cvt.rn.bf16x2.f32 %0, %1, %2;" : "=r"(h) : "f"(f1), "f"(f0));
    float l0 = f0 - __uint_as_float(h << 16);
    float l1 = f1 - __uint_as_float(h & 0xffff0000u);
    uint32_t l;
    asm("cvt.rn.bf16x2.f32 %0, %1, %2;" : "=r"(l) : "f"(l1), "f"(l0));
    hi2 = h; lo2 = l;
}

// ---------------------------------------------------------------------------
// Batched weight preconvert (ONE launch): W[K][N] -> Wt[N][K] bf16 hi/lo
// ---------------------------------------------------------------------------
__global__ void wconv_all(
    const float* __restrict__ Wf, const float* __restrict__ Wq,
    const float* __restrict__ Wk, const float* __restrict__ Wv,
    const float* __restrict__ Wo,
    unsigned short* __restrict__ Wfh, unsigned short* __restrict__ Wfl,
    unsigned short* __restrict__ Wqh, unsigned short* __restrict__ Wql,
    unsigned short* __restrict__ Wkh, unsigned short* __restrict__ Wkl,
    unsigned short* __restrict__ Wvh, unsigned short* __restrict__ Wvl,
    unsigned short* __restrict__ Woh, unsigned short* __restrict__ Wol)
{
    const float* W; unsigned short *Th, *Tl; int K;
    switch (blockIdx.z) {
        case 0:  W = Wf; Th = Wfh; Tl = Wfl; K = 1024; break;
        case 1:  W = Wq; Th = Wqh; Tl = Wql; K = 512;  break;
        case 2:  W = Wk; Th = Wkh; Tl = Wkl; K = 512;  break;
        case 3:  W = Wv; Th = Wvh; Tl = Wvl; K = 512;  break;
        default: W = Wo; Th = Woh; Tl = Wol; K = 512;  break;
    }
    int k0 = blockIdx.y * 32, n0 = blockIdx.x * 32;
    if (k0 >= K) return;
    __shared__ float t[32][33];
    int tx = threadIdx.x, ty = threadIdx.y;
    t[ty][tx] = W[(size_t)(k0 + ty) * D_ + n0 + tx];
    __syncthreads();
    float v = t[tx][ty];                 // W[k0+tx][n0+ty]
    unsigned short h, l;
    bsplit(v, h, l);
    size_t o = (size_t)(n0 + ty) * K + k0 + tx;
    Th[o] = h;
    Tl[o] = l;
}

// ---------------------------------------------------------------------------
// 3xBF16 tensor-core GEMM bits shared by all GEMM kernels.
// CTA 128x128, K-chunk 32, 8 warps (2x4) of 64x32, 2-stage cp.async pipeline.
// ---------------------------------------------------------------------------
#define GSTAGE   40960
#define GOFF_AH  0
#define GOFF_AL  10240
#define GOFF_BH  20480
#define GOFF_BL  30720
#define GM_SMEM  (2 * GSTAGE)

__device__ __forceinline__ void gemm_ldA(const float* A0, const float* A1,
                                         int sA0, int sA1, int Ksplit,
                                         int bm, int k0, int tid, float4* av)
{
#pragma unroll
    for (int i = 0; i < 4; i++) {
        int fid = tid + i * 256;
        int m = fid >> 3, kq = fid & 7;
        int kg = k0 + kq * 4;
        const float* src = (kg < Ksplit)
            ? A0 + (size_t)(bm + m) * sA0 + kg
            : A1 + (size_t)(bm + m) * sA1 + (kg - Ksplit);
        av[i] = *(const float4*)src;
    }
}
__device__ __forceinline__ void gemm_stA(unsigned char* stage, int tid,
                                         const float4* av)
{
#pragma unroll
    for (int i = 0; i < 4; i++) {
        int fid = tid + i * 256;
        int m = fid >> 3, kq = fid & 7;
        ushort4 h, l;
        bsplit(av[i].x, h.x, l.x);
        bsplit(av[i].y, h.y, l.y);
        bsplit(av[i].z, h.z, l.z);
        bsplit(av[i].w, h.w, l.w);
        *(ushort4*)(stage + GOFF_AH + m * 80 + kq * 8) = h;
        *(ushort4*)(stage + GOFF_AL + m * 80 + kq * 8) = l;
    }
}
__device__ __forceinline__ void gemm_cpPre(uint32_t stage_u32,
                                           uint32_t offH, uint32_t offL,
                                           const unsigned short* Th,
                                           const unsigned short* Tl,
                                           int row0, int K, int k0, int tid)
{
#pragma unroll
    for (int i = 0; i < 2; i++) {
        int fid = tid + i * 256;
        int r = fid >> 2, c16 = fid & 3;
        size_t gs = (size_t)(row0 + r) * K + k0 + c16 * 8;
        CP_ASYNC16(stage_u32 + offH + r * 80 + c16 * 16, (const char*)(Th + gs));
        CP_ASYNC16(stage_u32 + offL + r * 80 + c16 * 16, (const char*)(Tl + gs));
    }
}

// core compute on one staged chunk
__device__ __forceinline__ void gemm_chunk(uint32_t s0, uint32_t arow,
                                           uint32_t brow, float acc[4][4][4])
{
#pragma unroll
    for (int ks = 0; ks < 2; ks++) {
        uint32_t ah[4][4], al[4][4];
#pragma unroll
        for (int mt = 0; mt < 4; mt++) {
            ldm4(s0 + GOFF_AH + arow + mt * 1280 + ks * 32, ah[mt]);
            ldm4(s0 + GOFF_AL + arow + mt * 1280 + ks * 32, al[mt]);
        }
#pragma unroll
        for (int nb = 0; nb < 2; nb++) {
            uint32_t bh4[4], bl4[4];
            ldm4(s0 + GOFF_BH + brow + nb * 1280 + ks * 32, bh4);
            ldm4(s0 + GOFF_BL + brow + nb * 1280 + ks * 32, bl4);
            uint32_t th0[2] = {bh4[0], bh4[2]}, th1[2] = {bh4[1], bh4[3]};
            uint32_t tl0[2] = {bl4[0], bl4[2]}, tl1[2] = {bl4[1], bl4[3]};
#pragma unroll
            for (int mt = 0; mt < 4; mt++) {
                mma_bf16(acc[mt][2 * nb],     ah[mt], th0);
                mma_bf16(acc[mt][2 * nb + 1], ah[mt], th1);
                mma_bf16(acc[mt][2 * nb],     ah[mt], tl0);
                mma_bf16(acc[mt][2 * nb + 1], ah[mt], tl1);
                mma_bf16(acc[mt][2 * nb],     al[mt], th0);
                mma_bf16(acc[mt][2 * nb + 1], al[mt], th1);
            }
        }
    }
}

// ---------------------------------------------------------------------------
// General GEMM (fp32 A path): MODE 0: C fp32 row-major.
// MODE 2: bf16 hi/lo row-major.  MODE 3: bf16 hi/lo head-split [B,H,S,HD].
// ---------------------------------------------------------------------------
template <int MODE>
__global__ __launch_bounds__(256, 2) void mm_mma(
    const float* __restrict__ A0, const float* __restrict__ A1,
    int sA0, int sA1, int Ksplit,
    const unsigned short* __restrict__ Bh, const unsigned short* __restrict__ Bl,
    const float* __restrict__ bias, float* __restrict__ C,
    unsigned short* __restrict__ Ch, unsigned short* __restrict__ Cl,
    int N, int K)
{
    extern __shared__ __align__(16) unsigned char smem[];
    const uint32_t sb = smem_u32(smem);
    const int tid = threadIdx.x, lane = tid & 31, wid = tid >> 5;
    const int wy = wid >> 2, wx = wid & 3;
    const int bn = blockIdx.x * 128, bm = blockIdx.y * 128;
    const int NC = K / 32;

    float acc[4][4][4];
#pragma unroll
    for (int i = 0; i < 4; i++)
#pragma unroll
        for (int j = 0; j < 4; j++)
#pragma unroll
            for (int q = 0; q < 4; q++) acc[i][j][q] = 0.f;

    const uint32_t arow = (wy * 64 + (lane & 15)) * 80 + (lane >> 4) * 16;
    const uint32_t brow = (wx * 32 + (lane & 15)) * 80 + (lane >> 4) * 16;

    float4 av[4];
    gemm_ldA(A0, A1, sA0, sA1, Ksplit, bm, 0, tid, av);
    gemm_cpPre(sb, GOFF_BH, GOFF_BL, Bh, Bl, bn, K, 0, tid);
    CP_COMMIT();
    gemm_stA(smem, tid, av);

    for (int c = 0; c < NC; c++) {
        const int st = c & 1;
        const bool more = (c + 1 < NC);
        if (more) {
            gemm_ldA(A0, A1, sA0, sA1, Ksplit, bm, (c + 1) * 32, tid, av);
            gemm_cpPre(sb + ((c + 1) & 1) * GSTAGE, GOFF_BH, GOFF_BL,
                       Bh, Bl, bn, K, (c + 1) * 32, tid);
            CP_COMMIT();
        }
        if (more) { CP_WAIT1(); } else { CP_WAIT0(); }
        __syncthreads();
        gemm_chunk(sb + st * GSTAGE, arow, brow, acc);
        if (more) gemm_stA(smem + ((c + 1) & 1) * GSTAGE, tid, av);
        __syncthreads();
    }

#pragma unroll
    for (int mt = 0; mt < 4; mt++) {
#pragma unroll
        for (int nt = 0; nt < 4; nt++) {
            int r0 = bm + wy * 64 + mt * 16 + (lane >> 2);
            int col = bn + wx * 32 + nt * 8 + 2 * (lane & 3);
            float b0 = bias[col], b1 = bias[col + 1];
            float2 v0 = make_float2(acc[mt][nt][0] + b0, acc[mt][nt][1] + b1);
            float2 v1 = make_float2(acc[mt][nt][2] + b0, acc[mt][nt][3] + b1);
            if (MODE == 0) {
                *(float2*)(C + (size_t)r0 * N + col) = v0;
                *(float2*)(C + (size_t)(r0 + 8) * N + col) = v1;
            } else if (MODE == 2) {
                unsigned short hx, lx, hy, ly;
                bsplit(v0.x, hx, lx); bsplit(v0.y, hy, ly);
                *(ushort2*)(Ch + (size_t)r0 * N + col) = make_ushort2(hx, hy);
                *(ushort2*)(Cl + (size_t)r0 * N + col) = make_ushort2(lx, ly);
                bsplit(v1.x, hx, lx); bsplit(v1.y, hy, ly);
                *(ushort2*)(Ch + (size_t)(r0 + 8) * N + col) = make_ushort2(hx, hy);
                *(ushort2*)(Cl + (size_t)(r0 + 8) * N + col) = make_ushort2(lx, ly);
            } else {   // MODE 3
                int hh = col >> 6, dd = col & (HD_ - 1);
                int bb0 = r0 >> 11, ss0 = r0 & (S_ - 1);
                size_t o0 = (((size_t)bb0 * H_ + hh) * S_ + ss0) * HD_ + dd;
                unsigned short hx, lx, hy, ly;
                bsplit(v0.x, hx, lx); bsplit(v0.y, hy, ly);
                *(ushort2*)(Ch + o0) = make_ushort2(hx, hy);
                *(ushort2*)(Cl + o0) = make_ushort2(lx, ly);
                int r1 = r0 + 8;
                int bb1 = r1 >> 11, ss1 = r1 & (S_ - 1);
                size_t o1 = (((size_t)bb1 * H_ + hh) * S_ + ss1) * HD_ + dd;
                bsplit(v1.x, hx, lx); bsplit(v1.y, hy, ly);
                *(ushort2*)(Ch + o1) = make_ushort2(hx, hy);
                *(ushort2*)(Cl + o1) = make_ushort2(lx, ly);
            }
        }
    }
}

// ---------------------------------------------------------------------------
// Merged Q+K projection: one launch, grid.z selects {Q, K}.
// A = pre-split fused via cp.async; output head-split bf16 hi/lo.
// Q output scaled by 0.125 (exact 2^-3 — folds the softmax scale).
// ---------------------------------------------------------------------------
__global__ __launch_bounds__(256, 2) void mm_qk(
    const unsigned short* __restrict__ Fh, const unsigned short* __restrict__ Fl,
    const unsigned short* __restrict__ Wqh, const unsigned short* __restrict__ Wql,
    const unsigned short* __restrict__ Wkh, const unsigned short* __restrict__ Wkl,
    const float* __restrict__ bq, const float* __restrict__ bk,
    unsigned short* __restrict__ Qh, unsigned short* __restrict__ Ql,
    unsigned short* __restrict__ Kh, unsigned short* __restrict__ Kl)
{
    extern __shared__ __align__(16) unsigned char smem[];
    const uint32_t sb = smem_u32(smem);
    const int tid = threadIdx.x, lane = tid & 31, wid = tid >> 5;
    const int wy = wid >> 2, wx = wid & 3;
    const int bn = blockIdx.x * 128, bm = blockIdx.y * 128;
    const int z = blockIdx.z;
    const unsigned short* Bh = z ? Wkh : Wqh;
    const unsigned short* Bl = z ? Wkl : Wql;
    const float* bias = z ? bk : bq;
    unsigned short* Ch = z ? Kh : Qh;
    unsigned short* Cl = z ? Kl : Ql;
    const float sc = z ? 1.0f : 0.125f;
    const int K = D_, N = D_, NC = K / 32;

    float acc[4][4][4];
#pragma unroll
    for (int i = 0; i < 4; i++)
#pragma unroll
        for (int j = 0; j < 4; j++)
#pragma unroll
            for (int q = 0; q < 4; q++) acc[i][j][q] = 0.f;

    const uint32_t arow = (wy * 64 + (lane & 15)) * 80 + (lane >> 4) * 16;
    const uint32_t brow = (wx * 32 + (lane & 15)) * 80 + (lane >> 4) * 16;

    gemm_cpPre(sb, GOFF_AH, GOFF_AL, Fh, Fl, bm, K, 0, tid);
    gemm_cpPre(sb, GOFF_BH, GOFF_BL, Bh, Bl, bn, K, 0, tid);
    CP_COMMIT();

    for (int c = 0; c < NC; c++) {
        const int st = c & 1;
        const bool more = (c + 1 < NC);
        if (more) {
            uint32_t s1 = sb + ((c + 1) & 1) * GSTAGE;
            gemm_cpPre(s1, GOFF_AH, GOFF_AL, Fh, Fl, bm, K, (c + 1) * 32, tid);
            gemm_cpPre(s1, GOFF_BH, GOFF_BL, Bh, Bl, bn, K, (c + 1) * 32, tid);
            CP_COMMIT();
        }
        if (more) { CP_WAIT1(); } else { CP_WAIT0(); }
        __syncthreads();
        gemm_chunk(sb + st * GSTAGE, arow, brow, acc);
        __syncthreads();
    }

#pragma unroll
    for (int mt = 0; mt < 4; mt++) {
#pragma unroll
        for (int nt = 0; nt < 4; nt++) {
            int r0 = bm + wy * 64 + mt * 16 + (lane >> 2);
            int col = bn + wx * 32 + nt * 8 + 2 * (lane & 3);
            float b0 = bias[col], b1 = bias[col + 1];
            float2 v0 = make_float2((acc[mt][nt][0] + b0) * sc,
                                    (acc[mt][nt][1] + b1) * sc);
            float2 v1 = make_float2((acc[mt][nt][2] + b0) * sc,
                                    (acc[mt][nt][3] + b1) * sc);
            int hh = col >> 6, dd = col & (HD_ - 1);
            int bb0 = r0 >> 11, ss0 = r0 & (S_ - 1);
            size_t o0 = (((size_t)bb0 * H_ + hh) * S_ + ss0) * HD_ + dd;
            unsigned short hx, lx, hy, ly;
            bsplit(v0.x, hx, lx); bsplit(v0.y, hy, ly);
            *(ushort2*)(Ch + o0) = make_ushort2(hx, hy);
            *(ushort2*)(Cl + o0) = make_ushort2(lx, ly);
            int r1 = r0 + 8;
            int bb1 = r1 >> 11, ss1 = r1 & (S_ - 1);
            size_t o1 = (((size_t)bb1 * H_ + hh) * S_ + ss1) * HD_ + dd;
            bsplit(v1.x, hx, lx); bsplit(v1.y, hy, ly);
            *(ushort2*)(Ch + o1) = make_ushort2(hx, hy);
            *(ushort2*)(Cl + o1) = make_ushort2(lx, ly);
        }
    }
}

// ---------------------------------------------------------------------------
// Tensor-core flash attention, masked softmax + L1 renorm.
// CTA: 128 q-rows x one (b,h); 256 threads = 8 warps x 16 rows; 64-key blocks.
// Q fragments register-resident (loaded once); K/V/M double-buffered cp.async;
// V via ldmatrix.trans; scale pre-folded into Q; conditional max-rescale.
// ---------------------------------------------------------------------------
#define AQ_H 0
#define AQ_L 18432
#define ASTG_BASE 36864
#define AS_KH 0
#define AS_KL 9216
#define AS_VH 18432
#define AS_VL 27648
#define AS_M  36864
#define MPITCH 304
#define ASTG  (36864 + 128 * MPITCH)        // 75776
#define ATTN_SMEM (36864 + 2 * ASTG)        // 188416

__device__ __forceinline__ void attn_cp_stage(
    uint32_t sb, int s,
    const unsigned short* Kh, const unsigned short* Kl,
    const unsigned short* Vh, const unsigned short* Vl,
    const float* Mp, size_t bhS, int q0, int kk0, int tid)
{
    const uint32_t base = sb + ASTG_BASE + s * ASTG;
#pragma unroll
    for (int i = 0; i < 8; i++) {
        const int t = i >> 1;
        const int idx = tid + (i & 1) * 256;
        const int row = idx >> 3, c16 = idx & 7;
        const unsigned short* sp = (t == 0) ? Kh : (t == 1) ? Kl
                                 : (t == 2) ? Vh : Vl;
        CP_ASYNC16(base + t * 9216 + row * 144 + c16 * 16,
                   (const char*)(sp + (bhS + kk0 + row) * HD_ + c16 * 8));
    }
#pragma unroll
    for (int i = 0; i < 8; i++) {
        const int idx = tid + i * 256;
        const int row = idx >> 4, c16 = idx & 15;
        CP_ASYNC16(base + AS_M + row * MPITCH + c16 * 16,
                   (const char*)(Mp + (size_t)(q0 + row) * S_ + kk0 + c16 * 4));
    }
}

__global__ __launch_bounds__(256, 1) void attn_mma(
    const unsigned short* __restrict__ Qh, const unsigned short* __restrict__ Ql,
    const unsigned short* __restrict__ Kh, const unsigned short* __restrict__ Kl,
    const unsigned short* __restrict__ Vh, const unsigned short* __restrict__ Vl,
    const float* __restrict__ Mm, float* __restrict__ Out)
{
    extern __shared__ __align__(16) unsigned char smem[];
    const uint32_t sb = smem_u32(smem);

    const int q0 = blockIdx.x * 128;
    const int h  = blockIdx.y;
    const int b  = blockIdx.z;
    const int tid = threadIdx.x, lane = tid & 31, w = tid >> 5;
    const int qr = lane >> 2, qc = lane & 3;

    const size_t bhS = ((size_t)b * H_ + h) * S_;
    const float* Mp = Mm + (size_t)b * S_ * S_;

    // prologue: Q tile + stage 0 (K/V/M) via cp.async, one group
#pragma unroll
    for (int i = 0; i < 8; i++) {
        const int idx = tid + (i & 3) * 256;
        const int row = idx >> 3, c16 = idx & 7;
        const unsigned short* sp = (i < 4) ? Qh : Ql;
        const uint32_t off = (i < 4) ? AQ_H : AQ_L;
        CP_ASYNC16(sb + off + row * 144 + c16 * 16,
                   (const char*)(sp + (bhS + q0 + row) * HD_ + c16 * 8));
    }
    attn_cp_stage(sb, 0, Kh, Kl, Vh, Vl, Mp, bhS, q0, 0, tid);
    CP_COMMIT();

    float O[8][4];
#pragma unroll
    for (int t = 0; t < 8; t++)
#pragma unroll
        for (int j = 0; j < 4; j++) O[t][j] = 0.f;
    float m0 = -1e30f, m1 = -1e30f, Z0 = 0.f, Z1 = 0.f, T0 = 0.f, T1 = 0.f;

    const uint32_t qrow = (w * 16 + (lane & 15)) * 144 + (lane >> 4) * 16;
    const uint32_t klrow = (lane & 15) * 144 + (lane >> 4) * 16;

    uint32_t qah[4][4], qal[4][4];   // Q fragments, loaded once at kb==0

    const int NB = S_ / 64;
    for (int kb = 0; kb < NB; kb++) {
        const int st = kb & 1;
        const bool more = (kb + 1 < NB);
        if (more) {
            attn_cp_stage(sb, st ^ 1, Kh, Kl, Vh, Vl, Mp, bhS, q0,
                          (kb + 1) * 64, tid);
            CP_COMMIT();
            CP_WAIT1();
        } else {
            CP_WAIT0();
        }
        __syncthreads();

        if (kb == 0) {
#pragma unroll
            for (int ks = 0; ks < 4; ks++) {
                ldm4(sb + AQ_H + qrow + ks * 32, qah[ks]);
                ldm4(sb + AQ_L + qrow + ks * 32, qal[ks]);
            }
        }

        const uint32_t stg = sb + ASTG_BASE + st * ASTG;

        // ---- S = Q K^T (3xBF16; Q pre-scaled by 0.125) ----
        float S[8][4];
#pragma unroll
        for (int t = 0; t < 8; t++)
#pragma unroll
            for (int j = 0; j < 4; j++) S[t][j] = 0.f;
#pragma unroll
        for (int ks = 0; ks < 4; ks++) {
#pragma unroll
            for (int nb = 0; nb < 4; nb++) {
                uint32_t bh4[4], bl4[4];
                ldm4(stg + AS_KH + klrow + nb * 2304 + ks * 32, bh4);
                ldm4(stg + AS_KL + klrow + nb * 2304 + ks * 32, bl4);
                uint32_t th0[2] = {bh4[0], bh4[2]}, th1[2] = {bh4[1], bh4[3]};
                uint32_t tl0[2] = {bl4[0], bl4[2]}, tl1[2] = {bl4[1], bl4[3]};
                mma_bf16(S[2 * nb],     qah[ks], th0);
                mma_bf16(S[2 * nb + 1], qah[ks], th1);
                mma_bf16(S[2 * nb],     qah[ks], tl0);
                mma_bf16(S[2 * nb + 1], qah[ks], tl1);
                mma_bf16(S[2 * nb],     qal[ks], th0);
                mma_bf16(S[2 * nb + 1], qal[ks], th1);
            }
        }

        // ---- mask + online softmax (M pitch 304: conflict-free) ----
        const unsigned char* msp = smem + ASTG_BASE + st * ASTG + AS_M;
        const int mr0 = (w * 16 + qr) * MPITCH + qc * 8;
        float bm0 = -1e30f, bm1 = -1e30f;
        float mva[8], mvb[8], mvc[8], mvd[8];
#pragma unroll
        for (int t = 0; t < 8; t++) {
            float2 ma = *(const float2*)(msp + mr0 + t * 32);
            float2 mb = *(const float2*)(msp + mr0 + 8 * MPITCH + t * 32);
            mva[t] = ma.x; mvb[t] = ma.y; mvc[t] = mb.x; mvd[t] = mb.y;
            S[t][0] *= ma.x;
            S[t][1] *= ma.y;
            S[t][2] *= mb.x;
            S[t][3] *= mb.y;
            bm0 = fmaxf(bm0, fmaxf(S[t][0], S[t][1]));
            bm1 = fmaxf(bm1, fmaxf(S[t][2], S[t][3]));
        }
        bm0 = fmaxf(bm0, __shfl_xor_sync(0xffffffffu, bm0, 1));
        bm0 = fmaxf(bm0, __shfl_xor_sync(0xffffffffu, bm0, 2));
        bm1 = fmaxf(bm1, __shfl_xor_sync(0xffffffffu, bm1, 1));
        bm1 = fmaxf(bm1, __shfl_xor_sync(0xffffffffu, bm1, 2));
        if (bm0 > m0) {
            float f0 = __expf(m0 - bm0);
            m0 = bm0; Z0 *= f0; T0 *= f0;
#pragma unroll
            for (int t = 0; t < 8; t++) { O[t][0] *= f0; O[t][1] *= f0; }
        }
        if (bm1 > m1) {
            float f1 = __expf(m1 - bm1);
            m1 = bm1; Z1 *= f1; T1 *= f1;
#pragma unroll
            for (int t = 0; t < 8; t++) { O[t][2] *= f1; O[t][3] *= f1; }
        }
#pragma unroll
        for (int t = 0; t < 8; t++) {
            float e0 = __expf(S[t][0] - m0);
            float e1 = __expf(S[t][1] - m0);
            float e2 = __expf(S[t][2] - m1);
            float e3 = __expf(S[t][3] - m1);
            Z0 += e0 + e1; Z1 += e2 + e3;
            float p0 = e0 * mva[t], p1 = e1 * mvb[t];
            float p2 = e2 * mvc[t], p3 = e3 * mvd[t];
            T0 += p0 + p1; T1 += p2 + p3;
            S[t][0] = p0; S[t][1] = p1; S[t][2] = p2; S[t][3] = p3;
        }

        // ---- pack P to bf16 hi/lo A-fragments (packed cvt) ----
        uint32_t phi[4][4], plo[4][4];
#pragma unroll
        for (int kt = 0; kt < 4; kt++) {
            pack2(S[2 * kt][0],     S[2 * kt][1],     phi[kt][0], plo[kt][0]);
            pack2(S[2 * kt][2],     S[2 * kt][3],     phi[kt][1], plo[kt][1]);
            pack2(S[2 * kt + 1][0], S[2 * kt + 1][1], phi[kt][2], plo[kt][2]);
            pack2(S[2 * kt + 1][2], S[2 * kt + 1][3], phi[kt][3], plo[kt][3]);
        }

        // ---- O += P @ V  (V via ldmatrix.trans) ----
#pragma unroll
        for (int kt = 0; kt < 4; kt++) {
#pragma unroll
            for (int nb = 0; nb < 4; nb++) {
                uint32_t vh4[4], vl4[4];
                ldm4t(stg + AS_VH + kt * 2304 + klrow + nb * 32, vh4);
                ldm4t(stg + AS_VL + kt * 2304 + klrow + nb * 32, vl4);
                uint32_t th0[2] = {vh4[0], vh4[1]}, th1[2] = {vh4[2], vh4[3]};
                uint32_t tl0[2] = {vl4[0], vl4[1]}, tl1[2] = {vl4[2], vl4[3]};
                mma_bf16(O[2 * nb],     phi[kt], th0);
                mma_bf16(O[2 * nb + 1], phi[kt], th1);
                mma_bf16(O[2 * nb],     phi[kt], tl0);
                mma_bf16(O[2 * nb + 1], phi[kt], tl1);
                mma_bf16(O[2 * nb],     plo[kt], th0);
                mma_bf16(O[2 * nb + 1], plo[kt], th1);
            }
        }
        __syncthreads();
    }

    // ---- finalize ----
    T0 += __shfl_xor_sync(0xffffffffu, T0, 1);
    T0 += __shfl_xor_sync(0xffffffffu, T0, 2);
    T1 += __shfl_xor_sync(0xffffffffu, T1, 1);
    T1 += __shfl_xor_sync(0xffffffffu, T1, 2);
    Z0 += __shfl_xor_sync(0xffffffffu, Z0, 1);
    Z0 += __shfl_xor_sync(0xffffffffu, Z0, 2);
    Z1 += __shfl_xor_sync(0xffffffffu, Z1, 1);
    Z1 += __shfl_xor_sync(0xffffffffu, Z1, 2);
    float inv0 = 1.0f / (T0 + EPS_ * Z0);
    float inv1 = 1.0f / (T1 + EPS_ * Z1);

    int gr0 = q0 + w * 16 + qr;
#pragma unroll
    for (int t = 0; t < 8; t++) {
        int d = t * 8 + 2 * qc;
        float2 v0 = make_float2(O[t][0] * inv0, O[t][1] * inv0);
        float2 v1 = make_float2(O[t][2] * inv1, O[t][3] * inv1);
        *(float2*)(Out + ((size_t)b * S_ + gr0) * D_ + h * HD_ + d) = v0;
        *(float2*)(Out + ((size_t)b * S_ + gr0 + 8) * D_ + h * HD_ + d) = v1;
    }
}

// ---------------------------------------------------------------------------
// Host
// ---------------------------------------------------------------------------
extern "C" void kernel_launch(void* const* d_in, const int* in_sizes, int n_in,
                              void* d_out, int out_size)
{
    const float* gene = (const float*)d_in[0];
    const float* expr = (const float*)d_in[1];
    const float* Mm   = (const float*)d_in[2];
    const float* Wf   = (const float*)d_in[3];
    const float* bf   = (const float*)d_in[4];
    const float* Wq   = (const float*)d_in[5];
    const float* bq   = (const float*)d_in[6];
    const float* Wk   = (const float*)d_in[7];
    const float* bk   = (const float*)d_in[8];
    const float* Wv   = (const float*)d_in[9];
    const float* bv   = (const float*)d_in[10];
    const float* Wo   = (const float*)d_in[11];
    const float* bo   = (const float*)d_in[12];
    float* out = (float*)d_out;

    float* Ab;
    unsigned short *Qh, *Ql, *Kh, *Kl, *Vh, *Vl, *Fh, *Fl;
    unsigned short *Wfh, *Wfl, *Wqh, *Wql, *Wkh, *Wkl, *Wvh, *Wvl, *Woh, *Wol;
    cudaGetSymbolAddress((void**)&Ab,  g_attn);
    cudaGetSymbolAddress((void**)&Qh,  g_Qh);
    cudaGetSymbolAddress((void**)&Ql,  g_Ql);
    cudaGetSymbolAddress((void**)&Kh,  g_Kh);
    cudaGetSymbolAddress((void**)&Kl,  g_Kl);
    cudaGetSymbolAddress((void**)&Vh,  g_Vh);
    cudaGetSymbolAddress((void**)&Vl,  g_Vl);
    cudaGetSymbolAddress((void**)&Fh,  g_fus_h);
    cudaGetSymbolAddress((void**)&Fl,  g_fus_l);
    cudaGetSymbolAddress((void**)&Wfh, g_Wf_h);
    cudaGetSymbolAddress((void**)&Wfl, g_Wf_l);
    cudaGetSymbolAddress((void**)&Wqh, g_Wq_h);
    cudaGetSymbolAddress((void**)&Wql, g_Wq_l);
    cudaGetSymbolAddress((void**)&Wkh, g_Wk_h);
    cudaGetSymbolAddress((void**)&Wkl, g_Wk_l);
    cudaGetSymbolAddress((void**)&Wvh, g_Wv_h);
    cudaGetSymbolAddress((void**)&Wvl, g_Wv_l);
    cudaGetSymbolAddress((void**)&Woh, g_Wo_h);
    cudaGetSymbolAddress((void**)&Wol, g_Wo_l);

    cudaFuncSetAttribute(mm_mma<2>, cudaFuncAttributeMaxDynamicSharedMemorySize, GM_SMEM);
    cudaFuncSetAttribute(mm_mma<3>, cudaFuncAttributeMaxDynamicSharedMemorySize, GM_SMEM);
    cudaFuncSetAttribute(mm_mma<0>, cudaFuncAttributeMaxDynamicSharedMemorySize, GM_SMEM);
    cudaFuncSetAttribute(mm_qk, cudaFuncAttributeMaxDynamicSharedMemorySize, GM_SMEM);
    cudaFuncSetAttribute(attn_mma, cudaFuncAttributeMaxDynamicSharedMemorySize, ATTN_SMEM);

    // 1) all weight conversions in ONE launch
    wconv_all<<<dim3(16, 32, 5), dim3(32, 32)>>>(
        Wf, Wq, Wk, Wv, Wo,
        Wfh, Wfl, Wqh, Wql, Wkh, Wkl, Wvh, Wvl, Woh, Wol);

    dim3 gg(D_ / 128, ROWS_ / 128);   // (4, 64)

    // 2) fused = concat(gene, expr) @ Wf + bf  -> bf16 hi/lo row-major
    mm_mma<2><<<gg, 256, GM_SMEM>>>(gene, expr, D_, D_, D_,
                                    Wfh, Wfl, bf, nullptr, Fh, Fl,
                                    D_, 2 * D_);
    // 3) Q and K in ONE launch (Q pre-scaled by 0.125)
    mm_qk<<<dim3(4, 64, 2), 256, GM_SMEM>>>(Fh, Fl, Wqh, Wql, Wkh, Wkl,
                                            bq, bk, Qh, Ql, Kh, Kl);
    // 4) V from expr (fp32 A path) -> head-split bf16 hi/lo
    mm_mma<3><<<gg, 256, GM_SMEM>>>(expr, expr, D_, D_, D_,
                                    Wvh, Wvl, bv, nullptr, Vh, Vl,
                                    D_, D_);
    // 5) flash attention
    attn_mma<<<dim3(S_ / 128, H_, B_), 256, ATTN_SMEM>>>(Qh, Ql, Kh, Kl,
                                                         Vh, Vl, Mm, Ab);
    // 6) out = attn @ Wo + bo
    mm_mma<0><<<gg, 256, GM_SMEM>>>(Ab, Ab, D_, D_, D_,
                                    Woh, Wol, bo, out, nullptr, nullptr,
                                    D_, D_);
}